// round 1
// baseline (speedup 1.0000x reference)
#include <cuda_runtime.h>
#include <cuda_bf16.h>

// Problem constants
#define CB   8
#define HW   4096          // 64*64
#define CIN  512

// Scratch for rpn_conv1 [8, 384, 64, 64]  (allowed: __device__ global array)
static __device__ float g_rpn_conv1[(size_t)CB * 384 * HW];

// ---------------------------------------------------------------------------
// helpers
// ---------------------------------------------------------------------------
__device__ __forceinline__ unsigned f2tf(float x) {
    unsigned r;
    asm("cvt.rna.tf32.f32 %0, %1;" : "=r"(r) : "f"(x));
    return r;
}

__device__ __forceinline__ void mma8(float d[4], const unsigned a[4], const unsigned b[2]) {
    asm volatile(
        "mma.sync.aligned.m16n8k8.row.col.f32.tf32.tf32.f32 "
        "{%0,%1,%2,%3}, {%4,%5,%6,%7}, {%8,%9}, {%0,%1,%2,%3};\n"
        : "+f"(d[0]), "+f"(d[1]), "+f"(d[2]), "+f"(d[3])
        : "r"(a[0]), "r"(a[1]), "r"(a[2]), "r"(a[3]), "r"(b[0]), "r"(b[1]));
}

// ---------------------------------------------------------------------------
// Kernel 1: fused 1x1 conv 512 -> 512 (w_f rows 0..127, w_2 rows 128..511),
// ReLU, writes directly into d_out "feat" region [B,512,64,64].
// GEMM per batch: C[512 x 4096] = W[512 x 512] * In[512 x 4096]
// Block tile 128x128, K-tile 16. 256 threads = 8 warps (2M x 4N), warp 64x32.
// ---------------------------------------------------------------------------
__global__ __launch_bounds__(256, 2)
void k_conv1(const float* __restrict__ base_feat,
             const float* __restrict__ w_f, const float* __restrict__ b_f,
             const float* __restrict__ w_2, const float* __restrict__ b_2,
             float* __restrict__ out)
{
    const int n  = blockIdx.z;
    const int mt = blockIdx.y;               // 0..3 (M tiles of 128)
    const int n0 = blockIdx.x * 128;         // pixel tile base
    const float* A  = (mt == 0) ? w_f : (w_2 + (size_t)(mt - 1) * 128 * CIN);
    const float* bi = (mt == 0) ? b_f : (b_2 + (mt - 1) * 128);
    const float* Bp = base_feat + (size_t)n * CIN * HW + n0;

    __shared__ unsigned As[128][20];   // [m][k], pad->conflict-free frag loads
    __shared__ unsigned Bs[16][136];   // [k][n], stride 136 -> conflict-free

    const int tid  = threadIdx.x;
    const int warp = tid >> 5, lane = tid & 31;
    const int wm = (warp >> 2) * 64, wn = (warp & 3) * 32;
    const int g  = lane >> 2, t4 = lane & 3;

    float acc[4][4][4];
    #pragma unroll
    for (int i = 0; i < 4; i++)
        #pragma unroll
        for (int j = 0; j < 4; j++)
            #pragma unroll
            for (int e = 0; e < 4; e++) acc[i][j][e] = 0.f;

    for (int k0 = 0; k0 < CIN; k0 += 16) {
        float4 ar[2], br[2];
        #pragma unroll
        for (int i = 0; i < 2; i++) {
            int e = tid + i * 256;
            ar[i] = *(const float4*)(A + (size_t)(e >> 2) * CIN + k0 + (e & 3) * 4);
            br[i] = *(const float4*)(Bp + (size_t)(k0 + (e >> 5)) * HW + (e & 31) * 4);
        }
        __syncthreads();
        #pragma unroll
        for (int i = 0; i < 2; i++) {
            int e = tid + i * 256;
            unsigned* pa = &As[e >> 2][(e & 3) * 4];
            pa[0] = f2tf(ar[i].x); pa[1] = f2tf(ar[i].y);
            pa[2] = f2tf(ar[i].z); pa[3] = f2tf(ar[i].w);
            unsigned* pb = &Bs[e >> 5][(e & 31) * 4];
            pb[0] = f2tf(br[i].x); pb[1] = f2tf(br[i].y);
            pb[2] = f2tf(br[i].z); pb[3] = f2tf(br[i].w);
        }
        __syncthreads();
        #pragma unroll
        for (int ks = 0; ks < 2; ks++) {
            const int kk = ks * 8;
            unsigned a[4][4], b[4][2];
            #pragma unroll
            for (int mf = 0; mf < 4; mf++) {
                int r = wm + mf * 16;
                a[mf][0] = As[r + g][kk + t4];
                a[mf][1] = As[r + g + 8][kk + t4];
                a[mf][2] = As[r + g][kk + t4 + 4];
                a[mf][3] = As[r + g + 8][kk + t4 + 4];
            }
            #pragma unroll
            for (int nf = 0; nf < 4; nf++) {
                int c = wn + nf * 8 + g;
                b[nf][0] = Bs[kk + t4][c];
                b[nf][1] = Bs[kk + t4 + 4][c];
            }
            #pragma unroll
            for (int mf = 0; mf < 4; mf++)
                #pragma unroll
                for (int nf = 0; nf < 4; nf++)
                    mma8(acc[mf][nf], a[mf], b[nf]);
        }
    }

    float* outb = out + (size_t)n * CIN * HW + (size_t)mt * 128 * HW;
    #pragma unroll
    for (int mf = 0; mf < 4; mf++) {
        int r0 = wm + mf * 16 + g;
        float bv0 = bi[r0], bv1 = bi[r0 + 8];
        #pragma unroll
        for (int nf = 0; nf < 4; nf++) {
            int c = n0 + wn + nf * 8 + t4 * 2;
            float2 v0, v1;
            v0.x = fmaxf(acc[mf][nf][0] + bv0, 0.f);
            v0.y = fmaxf(acc[mf][nf][1] + bv0, 0.f);
            v1.x = fmaxf(acc[mf][nf][2] + bv1, 0.f);
            v1.y = fmaxf(acc[mf][nf][3] + bv1, 0.f);
            *(float2*)(outb + (size_t)r0 * HW + c)       = v0;
            *(float2*)(outb + (size_t)(r0 + 8) * HW + c) = v1;
        }
    }
}

// ---------------------------------------------------------------------------
// Kernel 2: 3x3 conv 128 -> 384 pad=1, ReLU -> g_rpn_conv1.
// Implicit GEMM: 9 taps x 128 channels = K 1152. Input = first 128 channels of
// each batch in the feat region of d_out (== convf_rpn).
// Border handling: per-element predicate (x+dx in [0,64), hw+dy*64+dx in [0,4096)).
// ---------------------------------------------------------------------------
__global__ __launch_bounds__(256, 2)
void k_conv3(const float* __restrict__ feat,      // d_out
             const float* __restrict__ w_c1, const float* __restrict__ b_c1)
{
    const int n  = blockIdx.z;
    const int m0 = blockIdx.y * 128;             // 0,128,256
    const int n0 = blockIdx.x * 128;
    const float* In = feat + (size_t)n * CIN * HW;   // channels 0..127

    __shared__ unsigned As[128][20];
    __shared__ unsigned Bs[16][136];

    const int tid  = threadIdx.x;
    const int warp = tid >> 5, lane = tid & 31;
    const int wm = (warp >> 2) * 64, wn = (warp & 3) * 32;
    const int g  = lane >> 2, t4 = lane & 3;

    float acc[4][4][4];
    #pragma unroll
    for (int i = 0; i < 4; i++)
        #pragma unroll
        for (int j = 0; j < 4; j++)
            #pragma unroll
            for (int e = 0; e < 4; e++) acc[i][j][e] = 0.f;

    for (int tap = 0; tap < 9; tap++) {
        const int dy = tap / 3 - 1, dx = tap % 3 - 1;
        const int hoff = dy * 64 + dx;
        for (int kc = 0; kc < 128; kc += 16) {
            float av[8], bv[8];
            #pragma unroll
            for (int i = 0; i < 8; i++) {
                int e = tid + i * 256;
                av[i] = w_c1[(size_t)(m0 + (e >> 4)) * 1152 + (kc + (e & 15)) * 9 + tap];
                int cc  = e & 127;
                int hw  = n0 + cc;
                int x   = hw & 63;
                int hw2 = hw + hoff;
                bool ok = ((unsigned)(x + dx) < 64u) && ((unsigned)hw2 < 4096u);
                bv[i] = ok ? In[(size_t)(kc + (e >> 7)) * HW + hw2] : 0.f;
            }
            __syncthreads();
            #pragma unroll
            for (int i = 0; i < 8; i++) {
                int e = tid + i * 256;
                As[e >> 4][e & 15]  = f2tf(av[i]);
                Bs[e >> 7][e & 127] = f2tf(bv[i]);
            }
            __syncthreads();
            #pragma unroll
            for (int ks = 0; ks < 2; ks++) {
                const int kk = ks * 8;
                unsigned a[4][4], b[4][2];
                #pragma unroll
                for (int mf = 0; mf < 4; mf++) {
                    int r = wm + mf * 16;
                    a[mf][0] = As[r + g][kk + t4];
                    a[mf][1] = As[r + g + 8][kk + t4];
                    a[mf][2] = As[r + g][kk + t4 + 4];
                    a[mf][3] = As[r + g + 8][kk + t4 + 4];
                }
                #pragma unroll
                for (int nf = 0; nf < 4; nf++) {
                    int c = wn + nf * 8 + g;
                    b[nf][0] = Bs[kk + t4][c];
                    b[nf][1] = Bs[kk + t4 + 4][c];
                }
                #pragma unroll
                for (int mf = 0; mf < 4; mf++)
                    #pragma unroll
                    for (int nf = 0; nf < 4; nf++)
                        mma8(acc[mf][nf], a[mf], b[nf]);
            }
        }
    }

    float* ob = g_rpn_conv1 + (size_t)n * 384 * HW;
    #pragma unroll
    for (int mf = 0; mf < 4; mf++) {
        int r0 = m0 + wm + mf * 16 + g;
        float bv0 = b_c1[r0], bv1 = b_c1[r0 + 8];
        #pragma unroll
        for (int nf = 0; nf < 4; nf++) {
            int c = n0 + wn + nf * 8 + t4 * 2;
            float2 v0, v1;
            v0.x = fmaxf(acc[mf][nf][0] + bv0, 0.f);
            v0.y = fmaxf(acc[mf][nf][1] + bv0, 0.f);
            v1.x = fmaxf(acc[mf][nf][2] + bv1, 0.f);
            v1.y = fmaxf(acc[mf][nf][3] + bv1, 0.f);
            *(float2*)(ob + (size_t)r0 * HW + c)       = v0;
            *(float2*)(ob + (size_t)(r0 + 8) * HW + c) = v1;
        }
    }
}

// ---------------------------------------------------------------------------
// Kernel 3: head. GEMM M=64 (rows 0..17 cls, 18..53 box, 54..63 zero-pad),
// K=384, N-tile 128. Then bias + paired softmax (c vs c+9) for cls, bias for
// box, and the two trailing zero scalars.
// 8 warps (2M x 4N), warp tile 32x32.
// ---------------------------------------------------------------------------
__global__ __launch_bounds__(256)
void k_head(const float* __restrict__ w_cls, const float* __restrict__ b_cls,
            const float* __restrict__ w_box, const float* __restrict__ b_box,
            float* __restrict__ out)
{
    const int n  = blockIdx.z;
    const int n0 = blockIdx.x * 128;
    const float* Bp = g_rpn_conv1 + (size_t)n * 384 * HW + n0;

    __shared__ unsigned As[64][20];
    __shared__ unsigned Bs[16][136];
    __shared__ float    Cs[64][132];

    const int tid  = threadIdx.x;
    const int warp = tid >> 5, lane = tid & 31;
    const int wm = (warp >> 2) * 32, wn = (warp & 3) * 32;
    const int g  = lane >> 2, t4 = lane & 3;

    float acc[2][4][4];
    #pragma unroll
    for (int i = 0; i < 2; i++)
        #pragma unroll
        for (int j = 0; j < 4; j++)
            #pragma unroll
            for (int e = 0; e < 4; e++) acc[i][j][e] = 0.f;

    for (int k0 = 0; k0 < 384; k0 += 16) {
        float av[4]; float4 br[2];
        #pragma unroll
        for (int i = 0; i < 4; i++) {
            int e = tid + i * 256;
            int r = e >> 4, c = e & 15;
            float v;
            if (r < 18)      v = w_cls[(size_t)r * 384 + k0 + c];
            else if (r < 54) v = w_box[(size_t)(r - 18) * 384 + k0 + c];
            else             v = 0.f;
            av[i] = v;
        }
        #pragma unroll
        for (int i = 0; i < 2; i++) {
            int e = tid + i * 256;
            br[i] = *(const float4*)(Bp + (size_t)(k0 + (e >> 5)) * HW + (e & 31) * 4);
        }
        __syncthreads();
        #pragma unroll
        for (int i = 0; i < 4; i++) {
            int e = tid + i * 256;
            As[e >> 4][e & 15] = f2tf(av[i]);
        }
        #pragma unroll
        for (int i = 0; i < 2; i++) {
            int e = tid + i * 256;
            unsigned* pb = &Bs[e >> 5][(e & 31) * 4];
            pb[0] = f2tf(br[i].x); pb[1] = f2tf(br[i].y);
            pb[2] = f2tf(br[i].z); pb[3] = f2tf(br[i].w);
        }
        __syncthreads();
        #pragma unroll
        for (int ks = 0; ks < 2; ks++) {
            const int kk = ks * 8;
            unsigned a[2][4], b[4][2];
            #pragma unroll
            for (int mf = 0; mf < 2; mf++) {
                int r = wm + mf * 16;
                a[mf][0] = As[r + g][kk + t4];
                a[mf][1] = As[r + g + 8][kk + t4];
                a[mf][2] = As[r + g][kk + t4 + 4];
                a[mf][3] = As[r + g + 8][kk + t4 + 4];
            }
            #pragma unroll
            for (int nf = 0; nf < 4; nf++) {
                int c = wn + nf * 8 + g;
                b[nf][0] = Bs[kk + t4][c];
                b[nf][1] = Bs[kk + t4 + 4][c];
            }
            #pragma unroll
            for (int mf = 0; mf < 2; mf++)
                #pragma unroll
                for (int nf = 0; nf < 4; nf++)
                    mma8(acc[mf][nf], a[mf], b[nf]);
        }
    }

    // Park scores in smem for the softmax pairing.
    #pragma unroll
    for (int mf = 0; mf < 2; mf++) {
        int r0 = wm + mf * 16 + g;
        #pragma unroll
        for (int nf = 0; nf < 4; nf++) {
            int c = wn + nf * 8 + t4 * 2;
            Cs[r0][c]         = acc[mf][nf][0];
            Cs[r0][c + 1]     = acc[mf][nf][1];
            Cs[r0 + 8][c]     = acc[mf][nf][2];
            Cs[r0 + 8][c + 1] = acc[mf][nf][3];
        }
    }
    __syncthreads();

    const size_t F1 = (size_t)CB * CIN * HW;           // cls prob base
    const size_t F2 = F1 + (size_t)CB * 18 * HW;       // bbox base
    const size_t F3 = F2 + (size_t)CB * 36 * HW;       // zeros base

    // cls: pairs (c, c+9) softmax over dim formed by reshape(B,2,576,64)
    for (int it = tid; it < 9 * 128; it += 256) {
        int c = it >> 7, j = it & 127;
        float s0 = Cs[c][j]     + b_cls[c];
        float s1 = Cs[c + 9][j] + b_cls[c + 9];
        float m  = fmaxf(s0, s1);
        float e0 = expf(s0 - m), e1 = expf(s1 - m);
        float inv = 1.f / (e0 + e1);
        out[F1 + (size_t)n * 18 * HW + (size_t)c * HW + n0 + j]       = e0 * inv;
        out[F1 + (size_t)n * 18 * HW + (size_t)(c + 9) * HW + n0 + j] = e1 * inv;
    }
    // box: bias only
    for (int it = tid; it < 36 * 128; it += 256) {
        int c = it >> 7, j = it & 127;
        out[F2 + (size_t)n * 36 * HW + (size_t)c * HW + n0 + j] = Cs[18 + c][j] + b_box[c];
    }
    // trailing scalar zeros (eval-mode losses)
    if (n == 0 && blockIdx.x == 0 && tid == 0) {
        out[F3]     = 0.f;
        out[F3 + 1] = 0.f;
    }
}

// ---------------------------------------------------------------------------
extern "C" void kernel_launch(void* const* d_in, const int* in_sizes, int n_in,
                              void* d_out, int out_size)
{
    const float* base  = (const float*)d_in[0];
    // d_in[1] im_info, d_in[2] gt_boxes: unused in eval mode
    const float* w_f   = (const float*)d_in[3];
    const float* b_f   = (const float*)d_in[4];
    const float* w_2   = (const float*)d_in[5];
    const float* b_2   = (const float*)d_in[6];
    const float* w_c1  = (const float*)d_in[7];
    const float* b_c1  = (const float*)d_in[8];
    const float* w_cls = (const float*)d_in[9];
    const float* b_cls = (const float*)d_in[10];
    const float* w_box = (const float*)d_in[11];
    const float* b_box = (const float*)d_in[12];
    float* out = (float*)d_out;

    dim3 blk(256);
    k_conv1<<<dim3(32, 4, CB), blk>>>(base, w_f, b_f, w_2, b_2, out);
    k_conv3<<<dim3(32, 3, CB), blk>>>(out, w_c1, b_c1);
    k_head <<<dim3(32, 1, CB), blk>>>(w_cls, b_cls, w_box, b_box, out);
}

// round 2
// speedup vs baseline: 1.0076x; 1.0076x over previous
#include <cuda_runtime.h>
#include <cuda_bf16.h>

// Problem constants
#define CB   8
#define HW   4096          // 64*64
#define CIN  512

// Scratch for rpn_conv1 [8, 384, 64, 64]  (allowed: __device__ global array)
static __device__ float g_rpn_conv1[(size_t)CB * 384 * HW];

// ---------------------------------------------------------------------------
// helpers
// ---------------------------------------------------------------------------
__device__ __forceinline__ unsigned f2tf(float x) {
    unsigned r;
    asm("cvt.rna.tf32.f32 %0, %1;" : "=r"(r) : "f"(x));
    return r;
}

__device__ __forceinline__ void mma8(float d[4], const unsigned a[4], const unsigned b[2]) {
    asm volatile(
        "mma.sync.aligned.m16n8k8.row.col.f32.tf32.tf32.f32 "
        "{%0,%1,%2,%3}, {%4,%5,%6,%7}, {%8,%9}, {%0,%1,%2,%3};\n"
        : "+f"(d[0]), "+f"(d[1]), "+f"(d[2]), "+f"(d[3])
        : "r"(a[0]), "r"(a[1]), "r"(a[2]), "r"(a[3]), "r"(b[0]), "r"(b[1]));
}

// ---------------------------------------------------------------------------
// Kernel 1: fused 1x1 conv 512 -> 512 (w_f rows 0..127, w_2 rows 128..511),
// ReLU, writes directly into d_out "feat" region [B,512,64,64].
// GEMM per batch: C[512 x 4096] = W[512 x 512] * In[512 x 4096]
// Block tile 128x128, K-tile 16. 256 threads = 8 warps (2M x 4N), warp 64x32.
// ---------------------------------------------------------------------------
__global__ __launch_bounds__(256, 2)
void k_conv1(const float* __restrict__ base_feat,
             const float* __restrict__ w_f, const float* __restrict__ b_f,
             const float* __restrict__ w_2, const float* __restrict__ b_2,
             float* __restrict__ out)
{
    const int n  = blockIdx.z;
    const int mt = blockIdx.y;               // 0..3 (M tiles of 128)
    const int n0 = blockIdx.x * 128;         // pixel tile base
    const float* A  = (mt == 0) ? w_f : (w_2 + (size_t)(mt - 1) * 128 * CIN);
    const float* bi = (mt == 0) ? b_f : (b_2 + (mt - 1) * 128);
    const float* Bp = base_feat + (size_t)n * CIN * HW + n0;

    __shared__ unsigned As[128][20];   // [m][k], pad->conflict-free frag loads
    __shared__ unsigned Bs[16][136];   // [k][n], stride 136 -> conflict-free

    const int tid  = threadIdx.x;
    const int warp = tid >> 5, lane = tid & 31;
    const int wm = (warp >> 2) * 64, wn = (warp & 3) * 32;
    const int g  = lane >> 2, t4 = lane & 3;

    float acc[4][4][4];
    #pragma unroll
    for (int i = 0; i < 4; i++)
        #pragma unroll
        for (int j = 0; j < 4; j++)
            #pragma unroll
            for (int e = 0; e < 4; e++) acc[i][j][e] = 0.f;

    for (int k0 = 0; k0 < CIN; k0 += 16) {
        float4 ar[2], br[2];
        #pragma unroll
        for (int i = 0; i < 2; i++) {
            int e = tid + i * 256;
            ar[i] = *(const float4*)(A + (size_t)(e >> 2) * CIN + k0 + (e & 3) * 4);
            br[i] = *(const float4*)(Bp + (size_t)(k0 + (e >> 5)) * HW + (e & 31) * 4);
        }
        __syncthreads();
        #pragma unroll
        for (int i = 0; i < 2; i++) {
            int e = tid + i * 256;
            unsigned* pa = &As[e >> 2][(e & 3) * 4];
            pa[0] = f2tf(ar[i].x); pa[1] = f2tf(ar[i].y);
            pa[2] = f2tf(ar[i].z); pa[3] = f2tf(ar[i].w);
            unsigned* pb = &Bs[e >> 5][(e & 31) * 4];
            pb[0] = f2tf(br[i].x); pb[1] = f2tf(br[i].y);
            pb[2] = f2tf(br[i].z); pb[3] = f2tf(br[i].w);
        }
        __syncthreads();
        #pragma unroll
        for (int ks = 0; ks < 2; ks++) {
            const int kk = ks * 8;
            unsigned a[4][4], b[4][2];
            #pragma unroll
            for (int mf = 0; mf < 4; mf++) {
                int r = wm + mf * 16;
                a[mf][0] = As[r + g][kk + t4];
                a[mf][1] = As[r + g + 8][kk + t4];
                a[mf][2] = As[r + g][kk + t4 + 4];
                a[mf][3] = As[r + g + 8][kk + t4 + 4];
            }
            #pragma unroll
            for (int nf = 0; nf < 4; nf++) {
                int c = wn + nf * 8 + g;
                b[nf][0] = Bs[kk + t4][c];
                b[nf][1] = Bs[kk + t4 + 4][c];
            }
            #pragma unroll
            for (int mf = 0; mf < 4; mf++)
                #pragma unroll
                for (int nf = 0; nf < 4; nf++)
                    mma8(acc[mf][nf], a[mf], b[nf]);
        }
    }

    float* outb = out + (size_t)n * CIN * HW + (size_t)mt * 128 * HW;
    #pragma unroll
    for (int mf = 0; mf < 4; mf++) {
        int r0 = wm + mf * 16 + g;
        float bv0 = bi[r0], bv1 = bi[r0 + 8];
        #pragma unroll
        for (int nf = 0; nf < 4; nf++) {
            int c = n0 + wn + nf * 8 + t4 * 2;
            float2 v0, v1;
            v0.x = fmaxf(acc[mf][nf][0] + bv0, 0.f);
            v0.y = fmaxf(acc[mf][nf][1] + bv0, 0.f);
            v1.x = fmaxf(acc[mf][nf][2] + bv1, 0.f);
            v1.y = fmaxf(acc[mf][nf][3] + bv1, 0.f);
            *(float2*)(outb + (size_t)r0 * HW + c)       = v0;
            *(float2*)(outb + (size_t)(r0 + 8) * HW + c) = v1;
        }
    }
}

// ---------------------------------------------------------------------------
// Kernel 2: 3x3 conv 128 -> 384 pad=1, ReLU -> g_rpn_conv1.
// Implicit GEMM: 9 taps x 128 channels = K 1152. Input = first 128 channels of
// each batch in the feat region of d_out (== convf_rpn).
// Border handling: per-element predicate (x+dx in [0,64), hw+dy*64+dx in [0,4096)).
// ---------------------------------------------------------------------------
__global__ __launch_bounds__(256, 2)
void k_conv3(const float* __restrict__ feat,      // d_out
             const float* __restrict__ w_c1, const float* __restrict__ b_c1)
{
    const int n  = blockIdx.z;
    const int m0 = blockIdx.y * 128;             // 0,128,256
    const int n0 = blockIdx.x * 128;
    const float* In = feat + (size_t)n * CIN * HW;   // channels 0..127

    __shared__ unsigned As[128][20];
    __shared__ unsigned Bs[16][136];

    const int tid  = threadIdx.x;
    const int warp = tid >> 5, lane = tid & 31;
    const int wm = (warp >> 2) * 64, wn = (warp & 3) * 32;
    const int g  = lane >> 2, t4 = lane & 3;

    float acc[4][4][4];
    #pragma unroll
    for (int i = 0; i < 4; i++)
        #pragma unroll
        for (int j = 0; j < 4; j++)
            #pragma unroll
            for (int e = 0; e < 4; e++) acc[i][j][e] = 0.f;

    for (int tap = 0; tap < 9; tap++) {
        const int dy = tap / 3 - 1, dx = tap % 3 - 1;
        const int hoff = dy * 64 + dx;
        for (int kc = 0; kc < 128; kc += 16) {
            float av[8], bv[8];
            #pragma unroll
            for (int i = 0; i < 8; i++) {
                int e = tid + i * 256;
                av[i] = w_c1[(size_t)(m0 + (e >> 4)) * 1152 + (kc + (e & 15)) * 9 + tap];
                int cc  = e & 127;
                int hw  = n0 + cc;
                int x   = hw & 63;
                int hw2 = hw + hoff;
                bool ok = ((unsigned)(x + dx) < 64u) && ((unsigned)hw2 < 4096u);
                bv[i] = ok ? In[(size_t)(kc + (e >> 7)) * HW + hw2] : 0.f;
            }
            __syncthreads();
            #pragma unroll
            for (int i = 0; i < 8; i++) {
                int e = tid + i * 256;
                As[e >> 4][e & 15]  = f2tf(av[i]);
                Bs[e >> 7][e & 127] = f2tf(bv[i]);
            }
            __syncthreads();
            #pragma unroll
            for (int ks = 0; ks < 2; ks++) {
                const int kk = ks * 8;
                unsigned a[4][4], b[4][2];
                #pragma unroll
                for (int mf = 0; mf < 4; mf++) {
                    int r = wm + mf * 16;
                    a[mf][0] = As[r + g][kk + t4];
                    a[mf][1] = As[r + g + 8][kk + t4];
                    a[mf][2] = As[r + g][kk + t4 + 4];
                    a[mf][3] = As[r + g + 8][kk + t4 + 4];
                }
                #pragma unroll
                for (int nf = 0; nf < 4; nf++) {
                    int c = wn + nf * 8 + g;
                    b[nf][0] = Bs[kk + t4][c];
                    b[nf][1] = Bs[kk + t4 + 4][c];
                }
                #pragma unroll
                for (int mf = 0; mf < 4; mf++)
                    #pragma unroll
                    for (int nf = 0; nf < 4; nf++)
                        mma8(acc[mf][nf], a[mf], b[nf]);
            }
        }
    }

    float* ob = g_rpn_conv1 + (size_t)n * 384 * HW;
    #pragma unroll
    for (int mf = 0; mf < 4; mf++) {
        int r0 = m0 + wm + mf * 16 + g;
        float bv0 = b_c1[r0], bv1 = b_c1[r0 + 8];
        #pragma unroll
        for (int nf = 0; nf < 4; nf++) {
            int c = n0 + wn + nf * 8 + t4 * 2;
            float2 v0, v1;
            v0.x = fmaxf(acc[mf][nf][0] + bv0, 0.f);
            v0.y = fmaxf(acc[mf][nf][1] + bv0, 0.f);
            v1.x = fmaxf(acc[mf][nf][2] + bv1, 0.f);
            v1.y = fmaxf(acc[mf][nf][3] + bv1, 0.f);
            *(float2*)(ob + (size_t)r0 * HW + c)       = v0;
            *(float2*)(ob + (size_t)(r0 + 8) * HW + c) = v1;
        }
    }
}

// ---------------------------------------------------------------------------
// Kernel 3: head. GEMM M=64 (rows 0..17 cls, 18..53 box, 54..63 zero-pad),
// K=384, N-tile 128. Then bias + paired softmax (c vs c+9) for cls, bias for
// box, and the two trailing zero scalars.
// 8 warps (2M x 4N), warp tile 32x32.
// ---------------------------------------------------------------------------
__global__ __launch_bounds__(256)
void k_head(const float* __restrict__ w_cls, const float* __restrict__ b_cls,
            const float* __restrict__ w_box, const float* __restrict__ b_box,
            float* __restrict__ out)
{
    const int n  = blockIdx.z;
    const int n0 = blockIdx.x * 128;
    const float* Bp = g_rpn_conv1 + (size_t)n * 384 * HW + n0;

    __shared__ unsigned As[64][20];
    __shared__ unsigned Bs[16][136];
    __shared__ float    Cs[64][132];

    const int tid  = threadIdx.x;
    const int warp = tid >> 5, lane = tid & 31;
    const int wm = (warp >> 2) * 32, wn = (warp & 3) * 32;
    const int g  = lane >> 2, t4 = lane & 3;

    float acc[2][4][4];
    #pragma unroll
    for (int i = 0; i < 2; i++)
        #pragma unroll
        for (int j = 0; j < 4; j++)
            #pragma unroll
            for (int e = 0; e < 4; e++) acc[i][j][e] = 0.f;

    for (int k0 = 0; k0 < 384; k0 += 16) {
        float av[4]; float4 br[2];
        #pragma unroll
        for (int i = 0; i < 4; i++) {
            int e = tid + i * 256;
            int r = e >> 4, c = e & 15;
            float v;
            if (r < 18)      v = w_cls[(size_t)r * 384 + k0 + c];
            else if (r < 54) v = w_box[(size_t)(r - 18) * 384 + k0 + c];
            else             v = 0.f;
            av[i] = v;
        }
        #pragma unroll
        for (int i = 0; i < 2; i++) {
            int e = tid + i * 256;
            br[i] = *(const float4*)(Bp + (size_t)(k0 + (e >> 5)) * HW + (e & 31) * 4);
        }
        __syncthreads();
        #pragma unroll
        for (int i = 0; i < 4; i++) {
            int e = tid + i * 256;
            As[e >> 4][e & 15] = f2tf(av[i]);
        }
        #pragma unroll
        for (int i = 0; i < 2; i++) {
            int e = tid + i * 256;
            unsigned* pb = &Bs[e >> 5][(e & 31) * 4];
            pb[0] = f2tf(br[i].x); pb[1] = f2tf(br[i].y);
            pb[2] = f2tf(br[i].z); pb[3] = f2tf(br[i].w);
        }
        __syncthreads();
        #pragma unroll
        for (int ks = 0; ks < 2; ks++) {
            const int kk = ks * 8;
            unsigned a[2][4], b[4][2];
            #pragma unroll
            for (int mf = 0; mf < 2; mf++) {
                int r = wm + mf * 16;
                a[mf][0] = As[r + g][kk + t4];
                a[mf][1] = As[r + g + 8][kk + t4];
                a[mf][2] = As[r + g][kk + t4 + 4];
                a[mf][3] = As[r + g + 8][kk + t4 + 4];
            }
            #pragma unroll
            for (int nf = 0; nf < 4; nf++) {
                int c = wn + nf * 8 + g;
                b[nf][0] = Bs[kk + t4][c];
                b[nf][1] = Bs[kk + t4 + 4][c];
            }
            #pragma unroll
            for (int mf = 0; mf < 2; mf++)
                #pragma unroll
                for (int nf = 0; nf < 4; nf++)
                    mma8(acc[mf][nf], a[mf], b[nf]);
        }
    }

    // Park scores in smem for the softmax pairing.
    #pragma unroll
    for (int mf = 0; mf < 2; mf++) {
        int r0 = wm + mf * 16 + g;
        #pragma unroll
        for (int nf = 0; nf < 4; nf++) {
            int c = wn + nf * 8 + t4 * 2;
            Cs[r0][c]         = acc[mf][nf][0];
            Cs[r0][c + 1]     = acc[mf][nf][1];
            Cs[r0 + 8][c]     = acc[mf][nf][2];
            Cs[r0 + 8][c + 1] = acc[mf][nf][3];
        }
    }
    __syncthreads();

    const size_t F1 = (size_t)CB * CIN * HW;           // cls prob base
    const size_t F2 = F1 + (size_t)CB * 18 * HW;       // bbox base
    const size_t F3 = F2 + (size_t)CB * 36 * HW;       // zeros base

    // cls: pairs (c, c+9) softmax over dim formed by reshape(B,2,576,64)
    for (int it = tid; it < 9 * 128; it += 256) {
        int c = it >> 7, j = it & 127;
        float s0 = Cs[c][j]     + b_cls[c];
        float s1 = Cs[c + 9][j] + b_cls[c + 9];
        float m  = fmaxf(s0, s1);
        float e0 = expf(s0 - m), e1 = expf(s1 - m);
        float inv = 1.f / (e0 + e1);
        out[F1 + (size_t)n * 18 * HW + (size_t)c * HW + n0 + j]       = e0 * inv;
        out[F1 + (size_t)n * 18 * HW + (size_t)(c + 9) * HW + n0 + j] = e1 * inv;
    }
    // box: bias only
    for (int it = tid; it < 36 * 128; it += 256) {
        int c = it >> 7, j = it & 127;
        out[F2 + (size_t)n * 36 * HW + (size_t)c * HW + n0 + j] = Cs[18 + c][j] + b_box[c];
    }
    // trailing scalar zeros (eval-mode losses)
    if (n == 0 && blockIdx.x == 0 && tid == 0) {
        out[F3]     = 0.f;
        out[F3 + 1] = 0.f;
    }
}

// ---------------------------------------------------------------------------
extern "C" void kernel_launch(void* const* d_in, const int* in_sizes, int n_in,
                              void* d_out, int out_size)
{
    const float* base  = (const float*)d_in[0];
    // d_in[1] im_info, d_in[2] gt_boxes: unused in eval mode
    const float* w_f   = (const float*)d_in[3];
    const float* b_f   = (const float*)d_in[4];
    const float* w_2   = (const float*)d_in[5];
    const float* b_2   = (const float*)d_in[6];
    const float* w_c1  = (const float*)d_in[7];
    const float* b_c1  = (const float*)d_in[8];
    const float* w_cls = (const float*)d_in[9];
    const float* b_cls = (const float*)d_in[10];
    const float* w_box = (const float*)d_in[11];
    const float* b_box = (const float*)d_in[12];
    float* out = (float*)d_out;

    dim3 blk(256);
    k_conv1<<<dim3(32, 4, CB), blk>>>(base, w_f, b_f, w_2, b_2, out);
    k_conv3<<<dim3(32, 3, CB), blk>>>(out, w_c1, b_c1);
    k_head <<<dim3(32, 1, CB), blk>>>(w_cls, b_cls, w_box, b_box, out);
}

// round 3
// speedup vs baseline: 1.0081x; 1.0006x over previous
#include <cuda_runtime.h>
#include <cuda_bf16.h>

// Problem constants
#define CB   8
#define HW   4096          // 64*64
#define CIN  512

// Scratch for rpn_conv1 [8, 384, 64, 64]  (allowed: __device__ global array)
static __device__ float g_rpn_conv1[(size_t)CB * 384 * HW];

// ---------------------------------------------------------------------------
// helpers
// ---------------------------------------------------------------------------
__device__ __forceinline__ unsigned f2tf(float x) {
    unsigned r;
    asm("cvt.rna.tf32.f32 %0, %1;" : "=r"(r) : "f"(x));
    return r;
}

__device__ __forceinline__ void mma8(float d[4], const unsigned a[4], const unsigned b[2]) {
    asm volatile(
        "mma.sync.aligned.m16n8k8.row.col.f32.tf32.tf32.f32 "
        "{%0,%1,%2,%3}, {%4,%5,%6,%7}, {%8,%9}, {%0,%1,%2,%3};\n"
        : "+f"(d[0]), "+f"(d[1]), "+f"(d[2]), "+f"(d[3])
        : "r"(a[0]), "r"(a[1]), "r"(a[2]), "r"(a[3]), "r"(b[0]), "r"(b[1]));
}

// ---------------------------------------------------------------------------
// Kernel 1: fused 1x1 conv 512 -> 512 (w_f rows 0..127, w_2 rows 128..511),
// ReLU, writes directly into d_out "feat" region [B,512,64,64].
// GEMM per batch: C[512 x 4096] = W[512 x 512] * In[512 x 4096]
// Block tile 128x128, K-tile 16. 256 threads = 8 warps (2M x 4N), warp 64x32.
// ---------------------------------------------------------------------------
__global__ __launch_bounds__(256, 2)
void k_conv1(const float* __restrict__ base_feat,
             const float* __restrict__ w_f, const float* __restrict__ b_f,
             const float* __restrict__ w_2, const float* __restrict__ b_2,
             float* __restrict__ out)
{
    const int n  = blockIdx.z;
    const int mt = blockIdx.y;               // 0..3 (M tiles of 128)
    const int n0 = blockIdx.x * 128;         // pixel tile base
    const float* A  = (mt == 0) ? w_f : (w_2 + (size_t)(mt - 1) * 128 * CIN);
    const float* bi = (mt == 0) ? b_f : (b_2 + (mt - 1) * 128);
    const float* Bp = base_feat + (size_t)n * CIN * HW + n0;

    __shared__ unsigned As[128][20];   // [m][k], pad->conflict-free frag loads
    __shared__ unsigned Bs[16][136];   // [k][n], stride 136 -> conflict-free

    const int tid  = threadIdx.x;
    const int warp = tid >> 5, lane = tid & 31;
    const int wm = (warp >> 2) * 64, wn = (warp & 3) * 32;
    const int g  = lane >> 2, t4 = lane & 3;

    float acc[4][4][4];
    #pragma unroll
    for (int i = 0; i < 4; i++)
        #pragma unroll
        for (int j = 0; j < 4; j++)
            #pragma unroll
            for (int e = 0; e < 4; e++) acc[i][j][e] = 0.f;

    for (int k0 = 0; k0 < CIN; k0 += 16) {
        float4 ar[2], br[2];
        #pragma unroll
        for (int i = 0; i < 2; i++) {
            int e = tid + i * 256;
            ar[i] = *(const float4*)(A + (size_t)(e >> 2) * CIN + k0 + (e & 3) * 4);
            br[i] = *(const float4*)(Bp + (size_t)(k0 + (e >> 5)) * HW + (e & 31) * 4);
        }
        __syncthreads();
        #pragma unroll
        for (int i = 0; i < 2; i++) {
            int e = tid + i * 256;
            unsigned* pa = &As[e >> 2][(e & 3) * 4];
            pa[0] = f2tf(ar[i].x); pa[1] = f2tf(ar[i].y);
            pa[2] = f2tf(ar[i].z); pa[3] = f2tf(ar[i].w);
            unsigned* pb = &Bs[e >> 5][(e & 31) * 4];
            pb[0] = f2tf(br[i].x); pb[1] = f2tf(br[i].y);
            pb[2] = f2tf(br[i].z); pb[3] = f2tf(br[i].w);
        }
        __syncthreads();
        #pragma unroll
        for (int ks = 0; ks < 2; ks++) {
            const int kk = ks * 8;
            unsigned a[4][4], b[4][2];
            #pragma unroll
            for (int mf = 0; mf < 4; mf++) {
                int r = wm + mf * 16;
                a[mf][0] = As[r + g][kk + t4];
                a[mf][1] = As[r + g + 8][kk + t4];
                a[mf][2] = As[r + g][kk + t4 + 4];
                a[mf][3] = As[r + g + 8][kk + t4 + 4];
            }
            #pragma unroll
            for (int nf = 0; nf < 4; nf++) {
                int c = wn + nf * 8 + g;
                b[nf][0] = Bs[kk + t4][c];
                b[nf][1] = Bs[kk + t4 + 4][c];
            }
            #pragma unroll
            for (int mf = 0; mf < 4; mf++)
                #pragma unroll
                for (int nf = 0; nf < 4; nf++)
                    mma8(acc[mf][nf], a[mf], b[nf]);
        }
    }

    float* outb = out + (size_t)n * CIN * HW + (size_t)mt * 128 * HW;
    #pragma unroll
    for (int mf = 0; mf < 4; mf++) {
        int r0 = wm + mf * 16 + g;
        float bv0 = bi[r0], bv1 = bi[r0 + 8];
        #pragma unroll
        for (int nf = 0; nf < 4; nf++) {
            int c = n0 + wn + nf * 8 + t4 * 2;
            float2 v0, v1;
            v0.x = fmaxf(acc[mf][nf][0] + bv0, 0.f);
            v0.y = fmaxf(acc[mf][nf][1] + bv0, 0.f);
            v1.x = fmaxf(acc[mf][nf][2] + bv1, 0.f);
            v1.y = fmaxf(acc[mf][nf][3] + bv1, 0.f);
            *(float2*)(outb + (size_t)r0 * HW + c)       = v0;
            *(float2*)(outb + (size_t)(r0 + 8) * HW + c) = v1;
        }
    }
}

// ---------------------------------------------------------------------------
// Kernel 2: 3x3 conv 128 -> 384 pad=1, ReLU -> g_rpn_conv1.
// Implicit GEMM: 9 taps x 128 channels = K 1152. Input = first 128 channels of
// each batch in the feat region of d_out (== convf_rpn).
// Border handling: per-element predicate (x+dx in [0,64), hw+dy*64+dx in [0,4096)).
// ---------------------------------------------------------------------------
__global__ __launch_bounds__(256, 2)
void k_conv3(const float* __restrict__ feat,      // d_out
             const float* __restrict__ w_c1, const float* __restrict__ b_c1)
{
    const int n  = blockIdx.z;
    const int m0 = blockIdx.y * 128;             // 0,128,256
    const int n0 = blockIdx.x * 128;
    const float* In = feat + (size_t)n * CIN * HW;   // channels 0..127

    __shared__ unsigned As[128][20];
    __shared__ unsigned Bs[16][136];

    const int tid  = threadIdx.x;
    const int warp = tid >> 5, lane = tid & 31;
    const int wm = (warp >> 2) * 64, wn = (warp & 3) * 32;
    const int g  = lane >> 2, t4 = lane & 3;

    float acc[4][4][4];
    #pragma unroll
    for (int i = 0; i < 4; i++)
        #pragma unroll
        for (int j = 0; j < 4; j++)
            #pragma unroll
            for (int e = 0; e < 4; e++) acc[i][j][e] = 0.f;

    for (int tap = 0; tap < 9; tap++) {
        const int dy = tap / 3 - 1, dx = tap % 3 - 1;
        const int hoff = dy * 64 + dx;
        for (int kc = 0; kc < 128; kc += 16) {
            float av[8], bv[8];
            #pragma unroll
            for (int i = 0; i < 8; i++) {
                int e = tid + i * 256;
                av[i] = w_c1[(size_t)(m0 + (e >> 4)) * 1152 + (kc + (e & 15)) * 9 + tap];
                int cc  = e & 127;
                int hw  = n0 + cc;
                int x   = hw & 63;
                int hw2 = hw + hoff;
                bool ok = ((unsigned)(x + dx) < 64u) && ((unsigned)hw2 < 4096u);
                bv[i] = ok ? In[(size_t)(kc + (e >> 7)) * HW + hw2] : 0.f;
            }
            __syncthreads();
            #pragma unroll
            for (int i = 0; i < 8; i++) {
                int e = tid + i * 256;
                As[e >> 4][e & 15]  = f2tf(av[i]);
                Bs[e >> 7][e & 127] = f2tf(bv[i]);
            }
            __syncthreads();
            #pragma unroll
            for (int ks = 0; ks < 2; ks++) {
                const int kk = ks * 8;
                unsigned a[4][4], b[4][2];
                #pragma unroll
                for (int mf = 0; mf < 4; mf++) {
                    int r = wm + mf * 16;
                    a[mf][0] = As[r + g][kk + t4];
                    a[mf][1] = As[r + g + 8][kk + t4];
                    a[mf][2] = As[r + g][kk + t4 + 4];
                    a[mf][3] = As[r + g + 8][kk + t4 + 4];
                }
                #pragma unroll
                for (int nf = 0; nf < 4; nf++) {
                    int c = wn + nf * 8 + g;
                    b[nf][0] = Bs[kk + t4][c];
                    b[nf][1] = Bs[kk + t4 + 4][c];
                }
                #pragma unroll
                for (int mf = 0; mf < 4; mf++)
                    #pragma unroll
                    for (int nf = 0; nf < 4; nf++)
                        mma8(acc[mf][nf], a[mf], b[nf]);
            }
        }
    }

    float* ob = g_rpn_conv1 + (size_t)n * 384 * HW;
    #pragma unroll
    for (int mf = 0; mf < 4; mf++) {
        int r0 = m0 + wm + mf * 16 + g;
        float bv0 = b_c1[r0], bv1 = b_c1[r0 + 8];
        #pragma unroll
        for (int nf = 0; nf < 4; nf++) {
            int c = n0 + wn + nf * 8 + t4 * 2;
            float2 v0, v1;
            v0.x = fmaxf(acc[mf][nf][0] + bv0, 0.f);
            v0.y = fmaxf(acc[mf][nf][1] + bv0, 0.f);
            v1.x = fmaxf(acc[mf][nf][2] + bv1, 0.f);
            v1.y = fmaxf(acc[mf][nf][3] + bv1, 0.f);
            *(float2*)(ob + (size_t)r0 * HW + c)       = v0;
            *(float2*)(ob + (size_t)(r0 + 8) * HW + c) = v1;
        }
    }
}

// ---------------------------------------------------------------------------
// Kernel 3: head. GEMM M=64 (rows 0..17 cls, 18..53 box, 54..63 zero-pad),
// K=384, N-tile 128. Then bias + paired softmax (c vs c+9) for cls, bias for
// box, and the two trailing zero scalars.
// 8 warps (2M x 4N), warp tile 32x32.
// ---------------------------------------------------------------------------
__global__ __launch_bounds__(256)
void k_head(const float* __restrict__ w_cls, const float* __restrict__ b_cls,
            const float* __restrict__ w_box, const float* __restrict__ b_box,
            float* __restrict__ out)
{
    const int n  = blockIdx.z;
    const int n0 = blockIdx.x * 128;
    const float* Bp = g_rpn_conv1 + (size_t)n * 384 * HW + n0;

    __shared__ unsigned As[64][20];
    __shared__ unsigned Bs[16][136];
    __shared__ float    Cs[64][132];

    const int tid  = threadIdx.x;
    const int warp = tid >> 5, lane = tid & 31;
    const int wm = (warp >> 2) * 32, wn = (warp & 3) * 32;
    const int g  = lane >> 2, t4 = lane & 3;

    float acc[2][4][4];
    #pragma unroll
    for (int i = 0; i < 2; i++)
        #pragma unroll
        for (int j = 0; j < 4; j++)
            #pragma unroll
            for (int e = 0; e < 4; e++) acc[i][j][e] = 0.f;

    for (int k0 = 0; k0 < 384; k0 += 16) {
        float av[4]; float4 br[2];
        #pragma unroll
        for (int i = 0; i < 4; i++) {
            int e = tid + i * 256;
            int r = e >> 4, c = e & 15;
            float v;
            if (r < 18)      v = w_cls[(size_t)r * 384 + k0 + c];
            else if (r < 54) v = w_box[(size_t)(r - 18) * 384 + k0 + c];
            else             v = 0.f;
            av[i] = v;
        }
        #pragma unroll
        for (int i = 0; i < 2; i++) {
            int e = tid + i * 256;
            br[i] = *(const float4*)(Bp + (size_t)(k0 + (e >> 5)) * HW + (e & 31) * 4);
        }
        __syncthreads();
        #pragma unroll
        for (int i = 0; i < 4; i++) {
            int e = tid + i * 256;
            As[e >> 4][e & 15] = f2tf(av[i]);
        }
        #pragma unroll
        for (int i = 0; i < 2; i++) {
            int e = tid + i * 256;
            unsigned* pb = &Bs[e >> 5][(e & 31) * 4];
            pb[0] = f2tf(br[i].x); pb[1] = f2tf(br[i].y);
            pb[2] = f2tf(br[i].z); pb[3] = f2tf(br[i].w);
        }
        __syncthreads();
        #pragma unroll
        for (int ks = 0; ks < 2; ks++) {
            const int kk = ks * 8;
            unsigned a[2][4], b[4][2];
            #pragma unroll
            for (int mf = 0; mf < 2; mf++) {
                int r = wm + mf * 16;
                a[mf][0] = As[r + g][kk + t4];
                a[mf][1] = As[r + g + 8][kk + t4];
                a[mf][2] = As[r + g][kk + t4 + 4];
                a[mf][3] = As[r + g + 8][kk + t4 + 4];
            }
            #pragma unroll
            for (int nf = 0; nf < 4; nf++) {
                int c = wn + nf * 8 + g;
                b[nf][0] = Bs[kk + t4][c];
                b[nf][1] = Bs[kk + t4 + 4][c];
            }
            #pragma unroll
            for (int mf = 0; mf < 2; mf++)
                #pragma unroll
                for (int nf = 0; nf < 4; nf++)
                    mma8(acc[mf][nf], a[mf], b[nf]);
        }
    }

    // Park scores in smem for the softmax pairing.
    #pragma unroll
    for (int mf = 0; mf < 2; mf++) {
        int r0 = wm + mf * 16 + g;
        #pragma unroll
        for (int nf = 0; nf < 4; nf++) {
            int c = wn + nf * 8 + t4 * 2;
            Cs[r0][c]         = acc[mf][nf][0];
            Cs[r0][c + 1]     = acc[mf][nf][1];
            Cs[r0 + 8][c]     = acc[mf][nf][2];
            Cs[r0 + 8][c + 1] = acc[mf][nf][3];
        }
    }
    __syncthreads();

    const size_t F1 = (size_t)CB * CIN * HW;           // cls prob base
    const size_t F2 = F1 + (size_t)CB * 18 * HW;       // bbox base
    const size_t F3 = F2 + (size_t)CB * 36 * HW;       // zeros base

    // cls: pairs (c, c+9) softmax over dim formed by reshape(B,2,576,64)
    for (int it = tid; it < 9 * 128; it += 256) {
        int c = it >> 7, j = it & 127;
        float s0 = Cs[c][j]     + b_cls[c];
        float s1 = Cs[c + 9][j] + b_cls[c + 9];
        float m  = fmaxf(s0, s1);
        float e0 = expf(s0 - m), e1 = expf(s1 - m);
        float inv = 1.f / (e0 + e1);
        out[F1 + (size_t)n * 18 * HW + (size_t)c * HW + n0 + j]       = e0 * inv;
        out[F1 + (size_t)n * 18 * HW + (size_t)(c + 9) * HW + n0 + j] = e1 * inv;
    }
    // box: bias only
    for (int it = tid; it < 36 * 128; it += 256) {
        int c = it >> 7, j = it & 127;
        out[F2 + (size_t)n * 36 * HW + (size_t)c * HW + n0 + j] = Cs[18 + c][j] + b_box[c];
    }
    // trailing scalar zeros (eval-mode losses)
    if (n == 0 && blockIdx.x == 0 && tid == 0) {
        out[F3]     = 0.f;
        out[F3 + 1] = 0.f;
    }
}

// ---------------------------------------------------------------------------
extern "C" void kernel_launch(void* const* d_in, const int* in_sizes, int n_in,
                              void* d_out, int out_size)
{
    const float* base  = (const float*)d_in[0];
    // d_in[1] im_info, d_in[2] gt_boxes: unused in eval mode
    const float* w_f   = (const float*)d_in[3];
    const float* b_f   = (const float*)d_in[4];
    const float* w_2   = (const float*)d_in[5];
    const float* b_2   = (const float*)d_in[6];
    const float* w_c1  = (const float*)d_in[7];
    const float* b_c1  = (const float*)d_in[8];
    const float* w_cls = (const float*)d_in[9];
    const float* b_cls = (const float*)d_in[10];
    const float* w_box = (const float*)d_in[11];
    const float* b_box = (const float*)d_in[12];
    float* out = (float*)d_out;

    dim3 blk(256);
    k_conv1<<<dim3(32, 4, CB), blk>>>(base, w_f, b_f, w_2, b_2, out);
    k_conv3<<<dim3(32, 3, CB), blk>>>(out, w_c1, b_c1);
    k_head <<<dim3(32, 1, CB), blk>>>(w_cls, b_cls, w_box, b_box, out);
}

// round 4
// speedup vs baseline: 1.0325x; 1.0242x over previous
#include <cuda_runtime.h>

// Problem constants
#define CB   8
#define HW   4096          // 64*64
#define CIN  512

// Scratch for rpn_conv1 [8, 384, 64, 64]
static __device__ float g_rpn_conv1[(size_t)CB * 384 * HW];

// ---------------------------------------------------------------------------
// helpers
// ---------------------------------------------------------------------------
__device__ __forceinline__ unsigned f2tf(float x) {
    unsigned r;
    asm("cvt.rna.tf32.f32 %0, %1;" : "=r"(r) : "f"(x));
    return r;
}

__device__ __forceinline__ void mma8(float d[4], const unsigned a[4], const unsigned b[2]) {
    asm volatile(
        "mma.sync.aligned.m16n8k8.row.col.f32.tf32.tf32.f32 "
        "{%0,%1,%2,%3}, {%4,%5,%6,%7}, {%8,%9}, {%0,%1,%2,%3};\n"
        : "+f"(d[0]), "+f"(d[1]), "+f"(d[2]), "+f"(d[3])
        : "r"(a[0]), "r"(a[1]), "r"(a[2]), "r"(a[3]), "r"(b[0]), "r"(b[1]));
}

__device__ __forceinline__ unsigned sptr(const void* p) {
    return (unsigned)__cvta_generic_to_shared(p);
}
__device__ __forceinline__ void cp16(unsigned d, const void* s, bool ok) {
    asm volatile("cp.async.cg.shared.global [%0], [%1], 16, %2;\n"
                 :: "r"(d), "l"(s), "r"(ok ? 16 : 0));
}
__device__ __forceinline__ void cpcommit() { asm volatile("cp.async.commit_group;\n"); }
__device__ __forceinline__ void cpwait1()  { asm volatile("cp.async.wait_group 1;\n"); }
__device__ __forceinline__ void cpwait0()  { asm volatile("cp.async.wait_group 0;\n"); }

// ---------------------------------------------------------------------------
// Kernel 1: fused 1x1 conv 512 -> 512 (w_f rows 0..127, w_2 rows 128..511),
// ReLU, writes into d_out "feat" region. GEMM C[512x4096] = W[512x512]*In.
// Block 128x128, K-tile 16, 2-stage cp.async double buffer.
// 8 warps (2M x 4N), warp tile 64x32. TF32 conversion at fragment load.
// ---------------------------------------------------------------------------
struct alignas(16) S1 { float As[2][128][20]; float Bs[2][16][136]; };

__global__ __launch_bounds__(256, 2)
void k_conv1(const float* __restrict__ base_feat,
             const float* __restrict__ w_f, const float* __restrict__ b_f,
             const float* __restrict__ w_2, const float* __restrict__ b_2,
             float* __restrict__ out)
{
    __shared__ S1 sm;
    const int n  = blockIdx.z;
    const int mt = blockIdx.y;
    const int n0 = blockIdx.x * 128;
    const float* A  = (mt == 0) ? w_f : (w_2 + (size_t)(mt - 1) * 128 * CIN);
    const float* bi = (mt == 0) ? b_f : (b_2 + (mt - 1) * 128);
    const float* Bp = base_feat + (size_t)n * CIN * HW + n0;

    const int tid  = threadIdx.x;
    const int warp = tid >> 5, lane = tid & 31;
    const int wm = (warp >> 2) * 64, wn = (warp & 3) * 32;
    const int g  = lane >> 2, t4 = lane & 3;

    auto load = [&](int k0, int buf) {
        #pragma unroll
        for (int i = 0; i < 2; i++) {
            int e = tid + i * 256;
            cp16(sptr(&sm.As[buf][e >> 2][(e & 3) * 4]),
                 A + (size_t)(e >> 2) * CIN + k0 + (e & 3) * 4, true);
            cp16(sptr(&sm.Bs[buf][e >> 5][(e & 31) * 4]),
                 Bp + (size_t)(k0 + (e >> 5)) * HW + (e & 31) * 4, true);
        }
        cpcommit();
    };

    float acc[4][4][4] = {};

    load(0, 0);
    for (int t = 0; t < 32; t++) {
        const int buf = t & 1;
        if (t < 31) { load((t + 1) * 16, buf ^ 1); cpwait1(); }
        else        { cpwait0(); }
        __syncthreads();
        #pragma unroll
        for (int ks = 0; ks < 2; ks++) {
            const int kk = ks * 8;
            unsigned a[4][4], b[4][2];
            #pragma unroll
            for (int mf = 0; mf < 4; mf++) {
                int r = wm + mf * 16;
                a[mf][0] = f2tf(sm.As[buf][r + g][kk + t4]);
                a[mf][1] = f2tf(sm.As[buf][r + g + 8][kk + t4]);
                a[mf][2] = f2tf(sm.As[buf][r + g][kk + t4 + 4]);
                a[mf][3] = f2tf(sm.As[buf][r + g + 8][kk + t4 + 4]);
            }
            #pragma unroll
            for (int nf = 0; nf < 4; nf++) {
                int c = wn + nf * 8 + g;
                b[nf][0] = f2tf(sm.Bs[buf][kk + t4][c]);
                b[nf][1] = f2tf(sm.Bs[buf][kk + t4 + 4][c]);
            }
            #pragma unroll
            for (int mf = 0; mf < 4; mf++)
                #pragma unroll
                for (int nf = 0; nf < 4; nf++)
                    mma8(acc[mf][nf], a[mf], b[nf]);
        }
        __syncthreads();
    }

    float* outb = out + (size_t)n * CIN * HW + (size_t)mt * 128 * HW;
    #pragma unroll
    for (int mf = 0; mf < 4; mf++) {
        int r0 = wm + mf * 16 + g;
        float bv0 = bi[r0], bv1 = bi[r0 + 8];
        #pragma unroll
        for (int nf = 0; nf < 4; nf++) {
            int c = n0 + wn + nf * 8 + t4 * 2;
            float2 v0, v1;
            v0.x = fmaxf(acc[mf][nf][0] + bv0, 0.f);
            v0.y = fmaxf(acc[mf][nf][1] + bv0, 0.f);
            v1.x = fmaxf(acc[mf][nf][2] + bv1, 0.f);
            v1.y = fmaxf(acc[mf][nf][3] + bv1, 0.f);
            *(float2*)(outb + (size_t)r0 * HW + c)       = v0;
            *(float2*)(outb + (size_t)(r0 + 8) * HW + c) = v1;
        }
    }
}

// ---------------------------------------------------------------------------
// Kernel 2: 3x3 conv 128 -> 384 pad=1, ReLU -> g_rpn_conv1.
// Per 16-channel K-chunk: load haloed input tile H[16][4 rows][64] ONCE
// (double-buffered cp.async, zero-filled OOB rows), then 9 taps read shifted
// views: input idx = p + 64 + (dy*64+dx), with only a per-thread x-edge mask.
// Weights prefetch through registers one tap ahead (single-buffered As).
// ---------------------------------------------------------------------------
struct alignas(16) S3 { float As[128][20]; float H[2][16][264]; };

__global__ __launch_bounds__(256, 2)
void k_conv3(const float* __restrict__ feat,      // d_out (channels 0..127 per batch)
             const float* __restrict__ w_c1, const float* __restrict__ b_c1)
{
    __shared__ S3 sm;
    const int n  = blockIdx.z;
    const int m0 = blockIdx.y * 128;             // 0,128,256
    const int n0 = blockIdx.x * 128;             // pixel tile (2 rows of 64)
    const int y0 = blockIdx.x * 2;               // first output row of tile
    const float* In = feat + (size_t)n * CIN * HW;

    const int tid  = threadIdx.x;
    const int warp = tid >> 5, lane = tid & 31;
    const int wm = (warp >> 2) * 64, wn = (warp & 3) * 32;
    const int g  = lane >> 2, t4 = lane & 3;

    auto loadH = [&](int kc, int buf) {
        #pragma unroll
        for (int i = 0; i < 4; i++) {
            int e = tid + i * 256;
            int k = e >> 6, rem = e & 63, r = rem >> 4, xq = rem & 15;
            int gy = y0 - 1 + r;
            bool ok = (unsigned)gy < 64u;
            cp16(sptr(&sm.H[buf][k][r * 64 + xq * 4]),
                 In + (size_t)(kc * 16 + k) * HW + gy * 64 + xq * 4, ok);
        }
        cpcommit();
    };

    // per-thread fixed pixel indices + x-edge masks
    int px[4]; bool xlo[4], xhi[4];
    #pragma unroll
    for (int nf = 0; nf < 4; nf++) {
        px[nf] = wn + nf * 8 + g;
        int x = px[nf] & 63;
        xlo[nf] = (x == 0);
        xhi[nf] = (x == 63);
    }

    float acc[4][4][4] = {};
    float aw[8];

    loadH(0, 0);
    // preload weights (kc=0, tap=0): k index = c*9 + tap
    #pragma unroll
    for (int i = 0; i < 8; i++) {
        int e = tid + i * 256;
        aw[i] = w_c1[(size_t)(m0 + (e >> 4)) * 1152 + (size_t)(e & 15) * 9 + 0];
    }

    for (int kc = 0; kc < 8; kc++) {
        const int buf = kc & 1;
        for (int tap = 0; tap < 9; tap++) {
            __syncthreads();                               // S1: prior compute done
            if (tap == 0 && kc < 7) loadH(kc + 1, buf ^ 1);
            #pragma unroll
            for (int i = 0; i < 8; i++) {
                int e = tid + i * 256;
                sm.As[e >> 4][e & 15] = aw[i];
            }
            // prefetch next tap's weights
            int nkc = kc, ntap = tap + 1;
            if (ntap == 9) { ntap = 0; nkc = kc + 1; }
            if (nkc < 8) {
                #pragma unroll
                for (int i = 0; i < 8; i++) {
                    int e = tid + i * 256;
                    aw[i] = w_c1[(size_t)(m0 + (e >> 4)) * 1152
                                 + (size_t)(nkc * 16 + (e & 15)) * 9 + ntap];
                }
            }
            if (tap == 0) { if (kc < 7) cpwait1(); else cpwait0(); }
            __syncthreads();                               // S2: As + H visible

            const int dy = tap / 3 - 1, dx = tap % 3 - 1;
            const int hoff = 64 + dy * 64 + dx;
            #pragma unroll
            for (int ks = 0; ks < 2; ks++) {
                const int kk = ks * 8;
                unsigned a[4][4], b[4][2];
                #pragma unroll
                for (int mf = 0; mf < 4; mf++) {
                    int r = wm + mf * 16;
                    a[mf][0] = f2tf(sm.As[r + g][kk + t4]);
                    a[mf][1] = f2tf(sm.As[r + g + 8][kk + t4]);
                    a[mf][2] = f2tf(sm.As[r + g][kk + t4 + 4]);
                    a[mf][3] = f2tf(sm.As[r + g + 8][kk + t4 + 4]);
                }
                #pragma unroll
                for (int nf = 0; nf < 4; nf++) {
                    bool ok = (dx == 0) || (dx < 0 ? !xlo[nf] : !xhi[nf]);
                    int idx = px[nf] + hoff;
                    b[nf][0] = ok ? f2tf(sm.H[buf][kk + t4][idx])     : 0u;
                    b[nf][1] = ok ? f2tf(sm.H[buf][kk + t4 + 4][idx]) : 0u;
                }
                #pragma unroll
                for (int mf = 0; mf < 4; mf++)
                    #pragma unroll
                    for (int nf = 0; nf < 4; nf++)
                        mma8(acc[mf][nf], a[mf], b[nf]);
            }
        }
    }

    float* ob = g_rpn_conv1 + (size_t)n * 384 * HW;
    #pragma unroll
    for (int mf = 0; mf < 4; mf++) {
        int r0 = m0 + wm + mf * 16 + g;
        float bv0 = b_c1[r0], bv1 = b_c1[r0 + 8];
        #pragma unroll
        for (int nf = 0; nf < 4; nf++) {
            int c = n0 + wn + nf * 8 + t4 * 2;
            float2 v0, v1;
            v0.x = fmaxf(acc[mf][nf][0] + bv0, 0.f);
            v0.y = fmaxf(acc[mf][nf][1] + bv0, 0.f);
            v1.x = fmaxf(acc[mf][nf][2] + bv1, 0.f);
            v1.y = fmaxf(acc[mf][nf][3] + bv1, 0.f);
            *(float2*)(ob + (size_t)r0 * HW + c)       = v0;
            *(float2*)(ob + (size_t)(r0 + 8) * HW + c) = v1;
        }
    }
}

// ---------------------------------------------------------------------------
// Kernel 3: head. GEMM M=64 (0..17 cls, 18..53 box, 54..63 pad), K=384,
// N-tile 128, cp.async double-buffered. Then bias + paired softmax (c, c+9)
// for cls, bias for box, plus the two trailing zero scalars.
// Cs aliases As/Bs (union) to fit static smem.
// ---------------------------------------------------------------------------
struct alignas(16) SH {
    union {
        struct { float As[2][64][20]; float Bs[2][16][136]; } gm;
        float Cs[64][132];
    } u;
};

__global__ __launch_bounds__(256)
void k_head(const float* __restrict__ w_cls, const float* __restrict__ b_cls,
            const float* __restrict__ w_box, const float* __restrict__ b_box,
            float* __restrict__ out)
{
    __shared__ SH sm;
    const int n  = blockIdx.z;
    const int n0 = blockIdx.x * 128;
    const float* Bp = g_rpn_conv1 + (size_t)n * 384 * HW + n0;

    const int tid  = threadIdx.x;
    const int warp = tid >> 5, lane = tid & 31;
    const int wm = (warp >> 2) * 32, wn = (warp & 3) * 32;
    const int g  = lane >> 2, t4 = lane & 3;

    auto load = [&](int k0, int buf) {
        {   // A: 64 rows x 16 k = 256 float4
            int r = tid >> 2, kq = (tid & 3) * 4;
            const float* src = w_cls;
            bool ok = true;
            if (r < 18)      src = w_cls + (size_t)r * 384 + k0 + kq;
            else if (r < 54) src = w_box + (size_t)(r - 18) * 384 + k0 + kq;
            else             ok = false;
            cp16(sptr(&sm.u.gm.As[buf][r][kq]), src, ok);
        }
        #pragma unroll
        for (int i = 0; i < 2; i++) {
            int e = tid + i * 256;
            cp16(sptr(&sm.u.gm.Bs[buf][e >> 5][(e & 31) * 4]),
                 Bp + (size_t)(k0 + (e >> 5)) * HW + (e & 31) * 4, true);
        }
        cpcommit();
    };

    float acc[2][4][4] = {};

    load(0, 0);
    for (int t = 0; t < 24; t++) {
        const int buf = t & 1;
        if (t < 23) { load((t + 1) * 16, buf ^ 1); cpwait1(); }
        else        { cpwait0(); }
        __syncthreads();
        #pragma unroll
        for (int ks = 0; ks < 2; ks++) {
            const int kk = ks * 8;
            unsigned a[2][4], b[4][2];
            #pragma unroll
            for (int mf = 0; mf < 2; mf++) {
                int r = wm + mf * 16;
                a[mf][0] = f2tf(sm.u.gm.As[buf][r + g][kk + t4]);
                a[mf][1] = f2tf(sm.u.gm.As[buf][r + g + 8][kk + t4]);
                a[mf][2] = f2tf(sm.u.gm.As[buf][r + g][kk + t4 + 4]);
                a[mf][3] = f2tf(sm.u.gm.As[buf][r + g + 8][kk + t4 + 4]);
            }
            #pragma unroll
            for (int nf = 0; nf < 4; nf++) {
                int c = wn + nf * 8 + g;
                b[nf][0] = f2tf(sm.u.gm.Bs[buf][kk + t4][c]);
                b[nf][1] = f2tf(sm.u.gm.Bs[buf][kk + t4 + 4][c]);
            }
            #pragma unroll
            for (int mf = 0; mf < 2; mf++)
                #pragma unroll
                for (int nf = 0; nf < 4; nf++)
                    mma8(acc[mf][nf], a[mf], b[nf]);
        }
        __syncthreads();   // also guards the Cs aliasing below on the last iter
    }

    // Park scores in smem (aliases As/Bs — safe: trailing sync above).
    #pragma unroll
    for (int mf = 0; mf < 2; mf++) {
        int r0 = wm + mf * 16 + g;
        #pragma unroll
        for (int nf = 0; nf < 4; nf++) {
            int c = wn + nf * 8 + t4 * 2;
            sm.u.Cs[r0][c]         = acc[mf][nf][0];
            sm.u.Cs[r0][c + 1]     = acc[mf][nf][1];
            sm.u.Cs[r0 + 8][c]     = acc[mf][nf][2];
            sm.u.Cs[r0 + 8][c + 1] = acc[mf][nf][3];
        }
    }
    __syncthreads();

    const size_t F1 = (size_t)CB * CIN * HW;           // cls prob base
    const size_t F2 = F1 + (size_t)CB * 18 * HW;       // bbox base
    const size_t F3 = F2 + (size_t)CB * 36 * HW;       // zeros base

    for (int it = tid; it < 9 * 128; it += 256) {
        int c = it >> 7, j = it & 127;
        float s0 = sm.u.Cs[c][j]     + b_cls[c];
        float s1 = sm.u.Cs[c + 9][j] + b_cls[c + 9];
        float m  = fmaxf(s0, s1);
        float e0 = expf(s0 - m), e1 = expf(s1 - m);
        float inv = 1.f / (e0 + e1);
        out[F1 + (size_t)n * 18 * HW + (size_t)c * HW + n0 + j]       = e0 * inv;
        out[F1 + (size_t)n * 18 * HW + (size_t)(c + 9) * HW + n0 + j] = e1 * inv;
    }
    for (int it = tid; it < 36 * 128; it += 256) {
        int c = it >> 7, j = it & 127;
        out[F2 + (size_t)n * 36 * HW + (size_t)c * HW + n0 + j] = sm.u.Cs[18 + c][j] + b_box[c];
    }
    if (n == 0 && blockIdx.x == 0 && tid == 0) {
        out[F3]     = 0.f;
        out[F3 + 1] = 0.f;
    }
}

// ---------------------------------------------------------------------------
extern "C" void kernel_launch(void* const* d_in, const int* in_sizes, int n_in,
                              void* d_out, int out_size)
{
    const float* base  = (const float*)d_in[0];
    const float* w_f   = (const float*)d_in[3];
    const float* b_f   = (const float*)d_in[4];
    const float* w_2   = (const float*)d_in[5];
    const float* b_2   = (const float*)d_in[6];
    const float* w_c1  = (const float*)d_in[7];
    const float* b_c1  = (const float*)d_in[8];
    const float* w_cls = (const float*)d_in[9];
    const float* b_cls = (const float*)d_in[10];
    const float* w_box = (const float*)d_in[11];
    const float* b_box = (const float*)d_in[12];
    float* out = (float*)d_out;

    dim3 blk(256);
    k_conv1<<<dim3(32, 4, CB), blk>>>(base, w_f, b_f, w_2, b_2, out);
    k_conv3<<<dim3(32, 3, CB), blk>>>(out, w_c1, b_c1);
    k_head <<<dim3(32, 1, CB), blk>>>(w_cls, b_cls, w_box, b_box, out);
}

// round 7
// speedup vs baseline: 1.4226x; 1.3778x over previous
#include <cuda_runtime.h>
#include <cstdint>

// Problem constants
#define CB   8
#define HW   4096          // 64*64
#define CIN  512

// Device scratch (allowed: __device__ globals)
static __device__ float g_rpn_conv1[(size_t)CB * 384 * HW]; // conv3 out (rounded)
static __device__ float g_featr[(size_t)CB * 128 * HW];     // rounded convf_rpn
static __device__ float g_wa[512 * 512];                    // rounded [w_f; w_2]
static __device__ float g_wt[9 * 384 * 128];                // rounded w_c1, tap-major
static __device__ float g_wh[64 * 384];                     // rounded [w_cls; w_box; 0]

// ---------------------------------------------------------------------------
// helpers
// ---------------------------------------------------------------------------
__device__ __forceinline__ unsigned f2tf(float x) {
    unsigned r;
    asm("cvt.rna.tf32.f32 %0, %1;" : "=r"(r) : "f"(x));
    return r;
}
__device__ __forceinline__ float rndf(float x) { return __uint_as_float(f2tf(x)); }

__device__ __forceinline__ void mma8(float d[4], const unsigned a[4], const unsigned b[2]) {
    asm volatile(
        "mma.sync.aligned.m16n8k8.row.col.f32.tf32.tf32.f32 "
        "{%0,%1,%2,%3}, {%4,%5,%6,%7}, {%8,%9}, {%0,%1,%2,%3};\n"
        : "+f"(d[0]), "+f"(d[1]), "+f"(d[2]), "+f"(d[3])
        : "r"(a[0]), "r"(a[1]), "r"(a[2]), "r"(a[3]), "r"(b[0]), "r"(b[1]));
}

__device__ __forceinline__ unsigned sptr(const void* p) {
    return (unsigned)__cvta_generic_to_shared(p);
}
__device__ __forceinline__ void cp16(unsigned d, const void* s, bool ok) {
    asm volatile("cp.async.cg.shared.global [%0], [%1], 16, %2;\n"
                 :: "r"(d), "l"(s), "r"(ok ? 16 : 0));
}
__device__ __forceinline__ void cpcommit() { asm volatile("cp.async.commit_group;\n"); }
__device__ __forceinline__ void cpwait1()  { asm volatile("cp.async.wait_group 1;\n"); }
__device__ __forceinline__ void cpwait0()  { asm volatile("cp.async.wait_group 0;\n"); }

// ---------------------------------------------------------------------------
// Prep kernel: round weights to tf32 once; transpose w_c1 to tap-major.
// ---------------------------------------------------------------------------
#define PREP_N1 262144              // 512*512
#define PREP_N2 442368              // 9*384*128
#define PREP_N3 24576               // 64*384
#define PREP_TOT (PREP_N1 + PREP_N2 + PREP_N3)

__global__ void k_prep(const float* __restrict__ w_f, const float* __restrict__ w_2,
                       const float* __restrict__ w_c1,
                       const float* __restrict__ w_cls, const float* __restrict__ w_box)
{
    int i = blockIdx.x * 256 + threadIdx.x;
    if (i < PREP_N1) {
        int m = i >> 9;
        float v = (m < 128) ? w_f[i] : w_2[i - 65536];
        g_wa[i] = rndf(v);
        return;
    }
    i -= PREP_N1;
    if (i < PREP_N2) {
        int tap = i / 49152, rem = i % 49152;
        int m = rem >> 7, c = rem & 127;
        g_wt[i] = rndf(w_c1[(size_t)m * 1152 + c * 9 + tap]);
        return;
    }
    i -= PREP_N2;
    if (i < PREP_N3) {
        int r = i / 384, k = i - r * 384;
        float v;
        if (r < 18)      v = w_cls[i];
        else if (r < 54) v = w_box[(r - 18) * 384 + k];
        else             v = 0.f;
        g_wh[i] = rndf(v);
    }
}

// ---------------------------------------------------------------------------
// Kernel 1: fused 1x1 conv 512 -> 512, ReLU -> d_out feat region.
// A = g_wa (pre-rounded) -> no cvt on A fragments. B = base_feat (raw,
// cp.async) -> cvt on B fragments only. mt==0 additionally writes rounded
// channels 0..127 to g_featr for conv3.
// ---------------------------------------------------------------------------
struct alignas(16) S1 { float As[2][128][20]; float Bs[2][16][136]; };

__global__ __launch_bounds__(256, 2)
void k_conv1(const float* __restrict__ base_feat,
             const float* __restrict__ b_f, const float* __restrict__ b_2,
             float* __restrict__ out)
{
    __shared__ S1 sm;
    const int n  = blockIdx.z;
    const int mt = blockIdx.y;
    const int n0 = blockIdx.x * 128;
    const float* A  = g_wa + (size_t)mt * 128 * CIN;
    const float* bi = (mt == 0) ? b_f : (b_2 + (mt - 1) * 128);
    const float* Bp = base_feat + (size_t)n * CIN * HW + n0;

    const int tid  = threadIdx.x;
    const int warp = tid >> 5, lane = tid & 31;
    const int wm = (warp >> 2) * 64, wn = (warp & 3) * 32;
    const int g  = lane >> 2, t4 = lane & 3;

    auto load = [&](int k0, int buf) {
        #pragma unroll
        for (int i = 0; i < 2; i++) {
            int e = tid + i * 256;
            cp16(sptr(&sm.As[buf][e >> 2][(e & 3) * 4]),
                 A + (size_t)(e >> 2) * CIN + k0 + (e & 3) * 4, true);
            cp16(sptr(&sm.Bs[buf][e >> 5][(e & 31) * 4]),
                 Bp + (size_t)(k0 + (e >> 5)) * HW + (e & 31) * 4, true);
        }
        cpcommit();
    };

    float acc[4][4][4] = {};

    load(0, 0);
    for (int t = 0; t < 32; t++) {
        const int buf = t & 1;
        if (t < 31) { load((t + 1) * 16, buf ^ 1); cpwait1(); }
        else        { cpwait0(); }
        __syncthreads();
        #pragma unroll
        for (int ks = 0; ks < 2; ks++) {
            const int kk = ks * 8;
            unsigned a[4][4], b[4][2];
            #pragma unroll
            for (int mf = 0; mf < 4; mf++) {
                int r = wm + mf * 16;
                a[mf][0] = __float_as_uint(sm.As[buf][r + g][kk + t4]);
                a[mf][1] = __float_as_uint(sm.As[buf][r + g + 8][kk + t4]);
                a[mf][2] = __float_as_uint(sm.As[buf][r + g][kk + t4 + 4]);
                a[mf][3] = __float_as_uint(sm.As[buf][r + g + 8][kk + t4 + 4]);
            }
            #pragma unroll
            for (int nf = 0; nf < 4; nf++) {
                int c = wn + nf * 8 + g;
                b[nf][0] = f2tf(sm.Bs[buf][kk + t4][c]);
                b[nf][1] = f2tf(sm.Bs[buf][kk + t4 + 4][c]);
            }
            #pragma unroll
            for (int mf = 0; mf < 4; mf++)
                #pragma unroll
                for (int nf = 0; nf < 4; nf++)
                    mma8(acc[mf][nf], a[mf], b[nf]);
        }
        __syncthreads();
    }

    float* outb = out + (size_t)n * CIN * HW + (size_t)mt * 128 * HW;
    float* fr   = g_featr + (size_t)n * 128 * HW;
    #pragma unroll
    for (int mf = 0; mf < 4; mf++) {
        int r0 = wm + mf * 16 + g;
        float bv0 = bi[r0], bv1 = bi[r0 + 8];
        #pragma unroll
        for (int nf = 0; nf < 4; nf++) {
            int c = n0 + wn + nf * 8 + t4 * 2;
            float2 v0, v1;
            v0.x = fmaxf(acc[mf][nf][0] + bv0, 0.f);
            v0.y = fmaxf(acc[mf][nf][1] + bv0, 0.f);
            v1.x = fmaxf(acc[mf][nf][2] + bv1, 0.f);
            v1.y = fmaxf(acc[mf][nf][3] + bv1, 0.f);
            *(float2*)(outb + (size_t)r0 * HW + c)       = v0;
            *(float2*)(outb + (size_t)(r0 + 8) * HW + c) = v1;
            if (mt == 0) {
                float2 r2a, r2b;
                r2a.x = rndf(v0.x); r2a.y = rndf(v0.y);
                r2b.x = rndf(v1.x); r2b.y = rndf(v1.y);
                *(float2*)(fr + (size_t)r0 * HW + c)       = r2a;
                *(float2*)(fr + (size_t)(r0 + 8) * HW + c) = r2b;
            }
        }
    }
}

// ---------------------------------------------------------------------------
// Kernel 2: 3x3 conv 128 -> 384 pad=1, ReLU -> g_rpn_conv1 (rounded).
// Pre-rounded inputs -> NO cvt and NO edge masking in the inner loop.
// H slice layout (per k, per buffer): [8 zeroed pad floats][4 rows of 68],
// rows hold x=0..63 in cols 0..63; cols 64..67 zeroed (right halo). The
// 8-float front pad makes "row 0, col -1" (x=0, dy=-1, dx=-1) read zero —
// the R6 bug read one float BEFORE the slice (garbage). All other OOB
// fragment reads land in zeroed halo cols / prev-row col 67 / zfilled rows.
// ---------------------------------------------------------------------------
#define H_ROW   68
#define H_PAD   8
#define H_SLICE 280                 // 8 pad + 4*68
#define H_BUFN  (16 * H_SLICE)      // 4480 floats per buffer
#define C3_AS_F (2 * 128 * 20)      // 5120 floats
#define C3_SMEM ((C3_AS_F + 2 * H_BUFN) * 4)   // 56320 bytes

__global__ __launch_bounds__(256, 2)
void k_conv3(const float* __restrict__ b_c1)
{
    extern __shared__ float ds[];
    float (*As)[128][20] = (float(*)[128][20])ds;
    float* Hb = ds + C3_AS_F;

    const int n  = blockIdx.z;
    const int m0 = blockIdx.y * 128;
    const int n0 = blockIdx.x * 128;
    const int y0 = blockIdx.x * 2;
    const float* In = g_featr + (size_t)n * 128 * HW;

    const int tid  = threadIdx.x;
    const int warp = tid >> 5, lane = tid & 31;
    const int wm = (warp >> 2) * 64, wn = (warp & 3) * 32;
    const int g  = lane >> 2, t4 = lane & 3;

    // zero pads: per (buf,k): front pad [0..7] and halo cols 64..67 of 4 rows
    // -> 24 floats; total 2*16*24 = 768
    for (int i = tid; i < 768; i += 256) {
        int buf = i / 384, r2 = i % 384;
        int k = r2 / 24, e = r2 % 24;
        int off;
        if (e < 8) off = e;                                   // front pad
        else { int rr = (e - 8) >> 2, cc = (e - 8) & 3;       // halo cols
               off = H_PAD + rr * H_ROW + 64 + cc; }
        Hb[buf * H_BUFN + k * H_SLICE + off] = 0.f;
    }

    auto loadA = [&](int kc, int tap, int buf) {
        #pragma unroll
        for (int j = 0; j < 2; j++) {
            int e = tid + j * 256;                 // 0..511
            int row = e >> 2, u = e & 3;
            cp16(sptr(&As[buf][row][u * 4]),
                 g_wt + ((size_t)tap * 384 + m0 + row) * 128 + kc * 16 + u * 4, true);
        }
    };
    auto loadH = [&](int kc, int buf) {
        #pragma unroll
        for (int j = 0; j < 4; j++) {
            int e = tid + j * 256;                 // 0..1023
            int k = e >> 6, rem = e & 63, r = rem >> 4, xu = rem & 15;
            int gy = y0 - 1 + r;
            cp16(sptr(&Hb[buf * H_BUFN + k * H_SLICE + H_PAD + r * H_ROW + xu * 4]),
                 In + (size_t)(kc * 16 + k) * HW + gy * 64 + xu * 4,
                 (unsigned)gy < 64u);
        }
    };

    // per-thread pixel base offsets into an H slice (center row = 1 + px>>6)
    int ib[4];
    #pragma unroll
    for (int nf = 0; nf < 4; nf++) {
        int px = wn + nf * 8 + g;
        ib[nf] = H_PAD + (1 + (px >> 6)) * H_ROW + (px & 63);
    }

    float acc[4][4][4] = {};

    loadA(0, 0, 0);
    loadH(0, 0);
    cpcommit();

    for (int it = 0; it < 72; it++) {
        const int kc = it / 9, tap = it - kc * 9;
        const int buf = it & 1;
        __syncthreads();                          // prior compute done (buffers free)
        if (it < 71) {
            int nkc = kc, ntap = tap + 1;
            if (ntap == 9) { ntap = 0; nkc++; }
            loadA(nkc, ntap, buf ^ 1);
            if (tap == 0 && kc < 7) loadH(kc + 1, (kc + 1) & 1);
            cpcommit();
            cpwait1();
        } else {
            cpwait0();
        }
        __syncthreads();                          // data visible to all

        const int dy = tap / 3 - 1, dx = tap % 3 - 1;
        const int hoff = dy * H_ROW + dx;
        const float* Hc = Hb + (kc & 1) * H_BUFN;

        #pragma unroll
        for (int ks = 0; ks < 2; ks++) {
            const int kk = ks * 8;
            unsigned a[4][4], b[4][2];
            #pragma unroll
            for (int mf = 0; mf < 4; mf++) {
                int r = wm + mf * 16;
                a[mf][0] = __float_as_uint(As[buf][r + g][kk + t4]);
                a[mf][1] = __float_as_uint(As[buf][r + g + 8][kk + t4]);
                a[mf][2] = __float_as_uint(As[buf][r + g][kk + t4 + 4]);
                a[mf][3] = __float_as_uint(As[buf][r + g + 8][kk + t4 + 4]);
            }
            #pragma unroll
            for (int nf = 0; nf < 4; nf++) {
                b[nf][0] = __float_as_uint(Hc[(kk + t4) * H_SLICE + ib[nf] + hoff]);
                b[nf][1] = __float_as_uint(Hc[(kk + t4 + 4) * H_SLICE + ib[nf] + hoff]);
            }
            #pragma unroll
            for (int mf = 0; mf < 4; mf++)
                #pragma unroll
                for (int nf = 0; nf < 4; nf++)
                    mma8(acc[mf][nf], a[mf], b[nf]);
        }
    }

    float* ob = g_rpn_conv1 + (size_t)n * 384 * HW;
    #pragma unroll
    for (int mf = 0; mf < 4; mf++) {
        int r0 = m0 + wm + mf * 16 + g;
        float bv0 = b_c1[r0], bv1 = b_c1[r0 + 8];
        #pragma unroll
        for (int nf = 0; nf < 4; nf++) {
            int c = n0 + wn + nf * 8 + t4 * 2;
            float2 v0, v1;
            v0.x = rndf(fmaxf(acc[mf][nf][0] + bv0, 0.f));
            v0.y = rndf(fmaxf(acc[mf][nf][1] + bv0, 0.f));
            v1.x = rndf(fmaxf(acc[mf][nf][2] + bv1, 0.f));
            v1.y = rndf(fmaxf(acc[mf][nf][3] + bv1, 0.f));
            *(float2*)(ob + (size_t)r0 * HW + c)       = v0;
            *(float2*)(ob + (size_t)(r0 + 8) * HW + c) = v1;
        }
    }
}

// ---------------------------------------------------------------------------
// Kernel 3: head. A = g_wh (pre-rounded, branchless), B = g_rpn_conv1
// (pre-rounded) -> no cvt anywhere. Bias + paired softmax (c, c+9) for cls,
// bias for box, two trailing zero scalars.
// ---------------------------------------------------------------------------
struct alignas(16) SH {
    union {
        struct { float As[2][64][20]; float Bs[2][16][136]; } gm;
        float Cs[64][132];
    } u;
};

__global__ __launch_bounds__(256)
void k_head(const float* __restrict__ b_cls, const float* __restrict__ b_box,
            float* __restrict__ out)
{
    __shared__ SH sm;
    const int n  = blockIdx.z;
    const int n0 = blockIdx.x * 128;
    const float* Bp = g_rpn_conv1 + (size_t)n * 384 * HW + n0;

    const int tid  = threadIdx.x;
    const int warp = tid >> 5, lane = tid & 31;
    const int wm = (warp >> 2) * 32, wn = (warp & 3) * 32;
    const int g  = lane >> 2, t4 = lane & 3;

    auto load = [&](int k0, int buf) {
        {
            int r = tid >> 2, kq = (tid & 3) * 4;
            cp16(sptr(&sm.u.gm.As[buf][r][kq]), g_wh + (size_t)r * 384 + k0 + kq, true);
        }
        #pragma unroll
        for (int i = 0; i < 2; i++) {
            int e = tid + i * 256;
            cp16(sptr(&sm.u.gm.Bs[buf][e >> 5][(e & 31) * 4]),
                 Bp + (size_t)(k0 + (e >> 5)) * HW + (e & 31) * 4, true);
        }
        cpcommit();
    };

    float acc[2][4][4] = {};

    load(0, 0);
    for (int t = 0; t < 24; t++) {
        const int buf = t & 1;
        if (t < 23) { load((t + 1) * 16, buf ^ 1); cpwait1(); }
        else        { cpwait0(); }
        __syncthreads();
        #pragma unroll
        for (int ks = 0; ks < 2; ks++) {
            const int kk = ks * 8;
            unsigned a[2][4], b[4][2];
            #pragma unroll
            for (int mf = 0; mf < 2; mf++) {
                int r = wm + mf * 16;
                a[mf][0] = __float_as_uint(sm.u.gm.As[buf][r + g][kk + t4]);
                a[mf][1] = __float_as_uint(sm.u.gm.As[buf][r + g + 8][kk + t4]);
                a[mf][2] = __float_as_uint(sm.u.gm.As[buf][r + g][kk + t4 + 4]);
                a[mf][3] = __float_as_uint(sm.u.gm.As[buf][r + g + 8][kk + t4 + 4]);
            }
            #pragma unroll
            for (int nf = 0; nf < 4; nf++) {
                int c = wn + nf * 8 + g;
                b[nf][0] = __float_as_uint(sm.u.gm.Bs[buf][kk + t4][c]);
                b[nf][1] = __float_as_uint(sm.u.gm.Bs[buf][kk + t4 + 4][c]);
            }
            #pragma unroll
            for (int mf = 0; mf < 2; mf++)
                #pragma unroll
                for (int nf = 0; nf < 4; nf++)
                    mma8(acc[mf][nf], a[mf], b[nf]);
        }
        __syncthreads();
    }

    #pragma unroll
    for (int mf = 0; mf < 2; mf++) {
        int r0 = wm + mf * 16 + g;
        #pragma unroll
        for (int nf = 0; nf < 4; nf++) {
            int c = wn + nf * 8 + t4 * 2;
            sm.u.Cs[r0][c]         = acc[mf][nf][0];
            sm.u.Cs[r0][c + 1]     = acc[mf][nf][1];
            sm.u.Cs[r0 + 8][c]     = acc[mf][nf][2];
            sm.u.Cs[r0 + 8][c + 1] = acc[mf][nf][3];
        }
    }
    __syncthreads();

    const size_t F1 = (size_t)CB * CIN * HW;
    const size_t F2 = F1 + (size_t)CB * 18 * HW;
    const size_t F3 = F2 + (size_t)CB * 36 * HW;

    for (int it = tid; it < 9 * 128; it += 256) {
        int c = it >> 7, j = it & 127;
        float s0 = sm.u.Cs[c][j]     + b_cls[c];
        float s1 = sm.u.Cs[c + 9][j] + b_cls[c + 9];
        float m  = fmaxf(s0, s1);
        float e0 = expf(s0 - m), e1 = expf(s1 - m);
        float inv = 1.f / (e0 + e1);
        out[F1 + (size_t)n * 18 * HW + (size_t)c * HW + n0 + j]       = e0 * inv;
        out[F1 + (size_t)n * 18 * HW + (size_t)(c + 9) * HW + n0 + j] = e1 * inv;
    }
    for (int it = tid; it < 36 * 128; it += 256) {
        int c = it >> 7, j = it & 127;
        out[F2 + (size_t)n * 36 * HW + (size_t)c * HW + n0 + j] = sm.u.Cs[18 + c][j] + b_box[c];
    }
    if (n == 0 && blockIdx.x == 0 && tid == 0) {
        out[F3]     = 0.f;
        out[F3 + 1] = 0.f;
    }
}

// ---------------------------------------------------------------------------
extern "C" void kernel_launch(void* const* d_in, const int* in_sizes, int n_in,
                              void* d_out, int out_size)
{
    const float* base  = (const float*)d_in[0];
    const float* w_f   = (const float*)d_in[3];
    const float* b_f   = (const float*)d_in[4];
    const float* w_2   = (const float*)d_in[5];
    const float* b_2   = (const float*)d_in[6];
    const float* w_c1  = (const float*)d_in[7];
    const float* b_c1  = (const float*)d_in[8];
    const float* w_cls = (const float*)d_in[9];
    const float* b_cls = (const float*)d_in[10];
    const float* w_box = (const float*)d_in[11];
    const float* b_box = (const float*)d_in[12];
    float* out = (float*)d_out;

    static bool attr_set = false;
    if (!attr_set) {
        cudaFuncSetAttribute(k_conv3, cudaFuncAttributeMaxDynamicSharedMemorySize, C3_SMEM);
        attr_set = true;
    }

    dim3 blk(256);
    k_prep <<<(PREP_TOT + 255) / 256, blk>>>(w_f, w_2, w_c1, w_cls, w_box);
    k_conv1<<<dim3(32, 4, CB), blk>>>(base, b_f, b_2, out);
    k_conv3<<<dim3(32, 3, CB), blk, C3_SMEM>>>(b_c1);
    k_head <<<dim3(32, 1, CB), blk>>>(b_cls, b_box, out);
}

// round 8
// speedup vs baseline: 1.4227x; 1.0001x over previous
#include <cuda_runtime.h>
#include <cstdint>

// Problem constants
#define CB   8
#define HW   4096          // 64*64
#define CIN  512

// Device scratch (allowed: __device__ globals)
static __device__ float g_rpn_conv1[(size_t)CB * 384 * HW]; // conv3 out (rounded)
static __device__ float g_featr[(size_t)CB * 128 * HW];     // rounded convf_rpn
static __device__ float g_wa[512 * 512];                    // rounded [w_f; w_2]
static __device__ float g_wt[9 * 384 * 128];                // rounded w_c1, tap-major
static __device__ float g_wh[64 * 384];                     // rounded [w_cls; w_box; 0]

// ---------------------------------------------------------------------------
// helpers
// ---------------------------------------------------------------------------
__device__ __forceinline__ unsigned f2tf(float x) {
    unsigned r;
    asm("cvt.rna.tf32.f32 %0, %1;" : "=r"(r) : "f"(x));
    return r;
}
__device__ __forceinline__ float rndf(float x) { return __uint_as_float(f2tf(x)); }

__device__ __forceinline__ void mma8(float d[4], const unsigned a[4], const unsigned b[2]) {
    asm volatile(
        "mma.sync.aligned.m16n8k8.row.col.f32.tf32.tf32.f32 "
        "{%0,%1,%2,%3}, {%4,%5,%6,%7}, {%8,%9}, {%0,%1,%2,%3};\n"
        : "+f"(d[0]), "+f"(d[1]), "+f"(d[2]), "+f"(d[3])
        : "r"(a[0]), "r"(a[1]), "r"(a[2]), "r"(a[3]), "r"(b[0]), "r"(b[1]));
}

__device__ __forceinline__ unsigned sptr(const void* p) {
    return (unsigned)__cvta_generic_to_shared(p);
}
__device__ __forceinline__ void cp16(unsigned d, const void* s, bool ok) {
    asm volatile("cp.async.cg.shared.global [%0], [%1], 16, %2;\n"
                 :: "r"(d), "l"(s), "r"(ok ? 16 : 0));
}
__device__ __forceinline__ void cpcommit() { asm volatile("cp.async.commit_group;\n"); }
__device__ __forceinline__ void cpwait1()  { asm volatile("cp.async.wait_group 1;\n"); }
__device__ __forceinline__ void cpwait0()  { asm volatile("cp.async.wait_group 0;\n"); }

// ---------------------------------------------------------------------------
// Prep kernel: round weights to tf32 once; transpose w_c1 to tap-major.
// ---------------------------------------------------------------------------
#define PREP_N1 262144              // 512*512
#define PREP_N2 442368              // 9*384*128
#define PREP_N3 24576               // 64*384
#define PREP_TOT (PREP_N1 + PREP_N2 + PREP_N3)

__global__ void k_prep(const float* __restrict__ w_f, const float* __restrict__ w_2,
                       const float* __restrict__ w_c1,
                       const float* __restrict__ w_cls, const float* __restrict__ w_box)
{
    int i = blockIdx.x * 256 + threadIdx.x;
    if (i < PREP_N1) {
        int m = i >> 9;
        float v = (m < 128) ? w_f[i] : w_2[i - 65536];
        g_wa[i] = rndf(v);
        return;
    }
    i -= PREP_N1;
    if (i < PREP_N2) {
        int tap = i / 49152, rem = i % 49152;
        int m = rem >> 7, c = rem & 127;
        g_wt[i] = rndf(w_c1[(size_t)m * 1152 + c * 9 + tap]);
        return;
    }
    i -= PREP_N2;
    if (i < PREP_N3) {
        int r = i / 384, k = i - r * 384;
        float v;
        if (r < 18)      v = w_cls[i];
        else if (r < 54) v = w_box[(r - 18) * 384 + k];
        else             v = 0.f;
        g_wh[i] = rndf(v);
    }
}

// ---------------------------------------------------------------------------
// Kernel 1: fused 1x1 conv 512 -> 512, ReLU -> d_out feat region.
// 3-stage cp.async ring, K-tile 32, ONE __syncthreads per iteration.
// Per iter t: wait_group(1) -> sync -> issue stage t+2 -> compute stage t%3.
// mt==0 also writes rounded channels 0..127 to g_featr for conv3.
// ---------------------------------------------------------------------------
#define C1_A_ST 4608                    // 128*36 floats
#define C1_B_ST 4352                    // 32*136 floats
#define C1_STAGE (C1_A_ST + C1_B_ST)    // 8960 floats
#define C1_SMEM (3 * C1_STAGE * 4)      // 107520 bytes

__global__ __launch_bounds__(256, 2)
void k_conv1(const float* __restrict__ base_feat,
             const float* __restrict__ b_f, const float* __restrict__ b_2,
             float* __restrict__ out)
{
    extern __shared__ float ds[];
    const int n  = blockIdx.z;
    const int mt = blockIdx.y;
    const int n0 = blockIdx.x * 128;
    const float* A  = g_wa + (size_t)mt * 128 * CIN;
    const float* bi = (mt == 0) ? b_f : (b_2 + (mt - 1) * 128);
    const float* Bp = base_feat + (size_t)n * CIN * HW + n0;

    const int tid  = threadIdx.x;
    const int warp = tid >> 5, lane = tid & 31;
    const int wm = (warp >> 2) * 64, wn = (warp & 3) * 32;
    const int g  = lane >> 2, t4 = lane & 3;

    auto loadT = [&](int t) {
        float* As = ds + (t % 3) * C1_STAGE;
        float* Bs = As + C1_A_ST;
        const int k0 = t * 32;
        #pragma unroll
        for (int i = 0; i < 4; i++) {
            int e = tid + i * 256;
            cp16(sptr(As + (e >> 3) * 36 + (e & 7) * 4),
                 A + (size_t)(e >> 3) * CIN + k0 + (e & 7) * 4, true);
            cp16(sptr(Bs + (e >> 5) * 136 + (e & 31) * 4),
                 Bp + (size_t)(k0 + (e >> 5)) * HW + (e & 31) * 4, true);
        }
        cpcommit();
    };

    float acc[4][4][4] = {};

    loadT(0);
    loadT(1);
    for (int t = 0; t < 16; t++) {
        if (t < 15) cpwait1(); else cpwait0();
        __syncthreads();
        if (t + 2 < 16) loadT(t + 2);

        const float* As = ds + (t % 3) * C1_STAGE;
        const float* Bs = As + C1_A_ST;
        #pragma unroll
        for (int ks = 0; ks < 4; ks++) {
            const int kk = ks * 8;
            unsigned a[4][4], b[4][2];
            #pragma unroll
            for (int mf = 0; mf < 4; mf++) {
                int r = wm + mf * 16;
                a[mf][0] = __float_as_uint(As[(r + g) * 36 + kk + t4]);
                a[mf][1] = __float_as_uint(As[(r + g + 8) * 36 + kk + t4]);
                a[mf][2] = __float_as_uint(As[(r + g) * 36 + kk + t4 + 4]);
                a[mf][3] = __float_as_uint(As[(r + g + 8) * 36 + kk + t4 + 4]);
            }
            #pragma unroll
            for (int nf = 0; nf < 4; nf++) {
                int c = wn + nf * 8 + g;
                b[nf][0] = f2tf(Bs[(kk + t4) * 136 + c]);
                b[nf][1] = f2tf(Bs[(kk + t4 + 4) * 136 + c]);
            }
            #pragma unroll
            for (int mf = 0; mf < 4; mf++)
                #pragma unroll
                for (int nf = 0; nf < 4; nf++)
                    mma8(acc[mf][nf], a[mf], b[nf]);
        }
    }

    float* outb = out + (size_t)n * CIN * HW + (size_t)mt * 128 * HW;
    float* fr   = g_featr + (size_t)n * 128 * HW;
    #pragma unroll
    for (int mf = 0; mf < 4; mf++) {
        int r0 = wm + mf * 16 + g;
        float bv0 = bi[r0], bv1 = bi[r0 + 8];
        #pragma unroll
        for (int nf = 0; nf < 4; nf++) {
            int c = n0 + wn + nf * 8 + t4 * 2;
            float2 v0, v1;
            v0.x = fmaxf(acc[mf][nf][0] + bv0, 0.f);
            v0.y = fmaxf(acc[mf][nf][1] + bv0, 0.f);
            v1.x = fmaxf(acc[mf][nf][2] + bv1, 0.f);
            v1.y = fmaxf(acc[mf][nf][3] + bv1, 0.f);
            *(float2*)(outb + (size_t)r0 * HW + c)       = v0;
            *(float2*)(outb + (size_t)(r0 + 8) * HW + c) = v1;
            if (mt == 0) {
                float2 r2a, r2b;
                r2a.x = rndf(v0.x); r2a.y = rndf(v0.y);
                r2b.x = rndf(v1.x); r2b.y = rndf(v1.y);
                *(float2*)(fr + (size_t)r0 * HW + c)       = r2a;
                *(float2*)(fr + (size_t)(r0 + 8) * HW + c) = r2b;
            }
        }
    }
}

// ---------------------------------------------------------------------------
// Kernel 2: 3x3 conv 128 -> 384 pad=1, ReLU -> g_rpn_conv1 (rounded).
// Pre-rounded inputs -> no cvt / no edge masking in the inner loop.
// A: 3-stage ring over iterations (kc,tap); H: 2 buffers at kc cadence.
// ONE __syncthreads per iteration. H slice: [8 zero pad][4 rows of 68],
// cols 64..67 zeroed (handles all border taps; front pad catches x=0,dx=-1,
// dy=-1).
// ---------------------------------------------------------------------------
#define H_ROW   68
#define H_PAD   8
#define H_SLICE 280                 // 8 pad + 4*68
#define H_BUFN  (16 * H_SLICE)      // 4480 floats per buffer
#define C3_AS_F (3 * 128 * 20)      // 7680 floats (3 stages)
#define C3_SMEM ((C3_AS_F + 2 * H_BUFN) * 4)   // 66560 bytes

__global__ __launch_bounds__(256, 2)
void k_conv3(const float* __restrict__ b_c1)
{
    extern __shared__ float ds[];
    float* Asb = ds;                 // 3 stages of [128][20]
    float* Hb  = ds + C3_AS_F;

    const int n  = blockIdx.z;
    const int m0 = blockIdx.y * 128;
    const int n0 = blockIdx.x * 128;
    const int y0 = blockIdx.x * 2;
    const float* In = g_featr + (size_t)n * 128 * HW;

    const int tid  = threadIdx.x;
    const int warp = tid >> 5, lane = tid & 31;
    const int wm = (warp >> 2) * 64, wn = (warp & 3) * 32;
    const int g  = lane >> 2, t4 = lane & 3;

    // zero pads: per (buf,k): front pad [0..7] + halo cols 64..67 of 4 rows
    for (int i = tid; i < 768; i += 256) {
        int buf = i / 384, r2 = i % 384;
        int k = r2 / 24, e = r2 % 24;
        int off;
        if (e < 8) off = e;
        else { int rr = (e - 8) >> 2, cc = (e - 8) & 3;
               off = H_PAD + rr * H_ROW + 64 + cc; }
        Hb[buf * H_BUFN + k * H_SLICE + off] = 0.f;
    }

    auto loadA = [&](int t) {                     // t = iteration index
        int kc = t / 9, tap = t - kc * 9;
        float* As = Asb + (t % 3) * (128 * 20);
        #pragma unroll
        for (int j = 0; j < 2; j++) {
            int e = tid + j * 256;                 // 0..511
            int row = e >> 2, u = e & 3;
            cp16(sptr(As + row * 20 + u * 4),
                 g_wt + ((size_t)tap * 384 + m0 + row) * 128 + kc * 16 + u * 4, true);
        }
    };
    auto loadH = [&](int kc, int buf) {
        #pragma unroll
        for (int j = 0; j < 4; j++) {
            int e = tid + j * 256;                 // 0..1023
            int k = e >> 6, rem = e & 63, r = rem >> 4, xu = rem & 15;
            int gy = y0 - 1 + r;
            cp16(sptr(&Hb[buf * H_BUFN + k * H_SLICE + H_PAD + r * H_ROW + xu * 4]),
                 In + (size_t)(kc * 16 + k) * HW + gy * 64 + xu * 4,
                 (unsigned)gy < 64u);
        }
    };

    // per-thread pixel base offsets into an H slice (center row = 1 + px>>6)
    int ib[4];
    #pragma unroll
    for (int nf = 0; nf < 4; nf++) {
        int px = wn + nf * 8 + g;
        ib[nf] = H_PAD + (1 + (px >> 6)) * H_ROW + (px & 63);
    }

    float acc[4][4][4] = {};

    // prologue: g0 = {A(0), H(0)}, g1 = {A(1)}
    loadA(0); loadH(0, 0); cpcommit();
    loadA(1); cpcommit();

    for (int it = 0; it < 72; it++) {
        const int kc = it / 9, tap = it - kc * 9;
        if (it < 71) cpwait1(); else cpwait0();
        __syncthreads();
        if (it + 2 < 72) {
            loadA(it + 2);
            if (tap == 0 && kc < 7) loadH(kc + 1, (kc + 1) & 1);
            cpcommit();
        }

        const int dy = tap / 3 - 1, dx = tap % 3 - 1;
        const int hoff = dy * H_ROW + dx;
        const float* As = Asb + (it % 3) * (128 * 20);
        const float* Hc = Hb + (kc & 1) * H_BUFN;

        #pragma unroll
        for (int ks = 0; ks < 2; ks++) {
            const int kk = ks * 8;
            unsigned a[4][4], b[4][2];
            #pragma unroll
            for (int mf = 0; mf < 4; mf++) {
                int r = wm + mf * 16;
                a[mf][0] = __float_as_uint(As[(r + g) * 20 + kk + t4]);
                a[mf][1] = __float_as_uint(As[(r + g + 8) * 20 + kk + t4]);
                a[mf][2] = __float_as_uint(As[(r + g) * 20 + kk + t4 + 4]);
                a[mf][3] = __float_as_uint(As[(r + g + 8) * 20 + kk + t4 + 4]);
            }
            #pragma unroll
            for (int nf = 0; nf < 4; nf++) {
                b[nf][0] = __float_as_uint(Hc[(kk + t4) * H_SLICE + ib[nf] + hoff]);
                b[nf][1] = __float_as_uint(Hc[(kk + t4 + 4) * H_SLICE + ib[nf] + hoff]);
            }
            #pragma unroll
            for (int mf = 0; mf < 4; mf++)
                #pragma unroll
                for (int nf = 0; nf < 4; nf++)
                    mma8(acc[mf][nf], a[mf], b[nf]);
        }
    }

    float* ob = g_rpn_conv1 + (size_t)n * 384 * HW;
    #pragma unroll
    for (int mf = 0; mf < 4; mf++) {
        int r0 = m0 + wm + mf * 16 + g;
        float bv0 = b_c1[r0], bv1 = b_c1[r0 + 8];
        #pragma unroll
        for (int nf = 0; nf < 4; nf++) {
            int c = n0 + wn + nf * 8 + t4 * 2;
            float2 v0, v1;
            v0.x = rndf(fmaxf(acc[mf][nf][0] + bv0, 0.f));
            v0.y = rndf(fmaxf(acc[mf][nf][1] + bv0, 0.f));
            v1.x = rndf(fmaxf(acc[mf][nf][2] + bv1, 0.f));
            v1.y = rndf(fmaxf(acc[mf][nf][3] + bv1, 0.f));
            *(float2*)(ob + (size_t)r0 * HW + c)       = v0;
            *(float2*)(ob + (size_t)(r0 + 8) * HW + c) = v1;
        }
    }
}

// ---------------------------------------------------------------------------
// Kernel 3: head. 3-stage ring, K-tile 32, one sync per iteration.
// A = g_wh (pre-rounded, branchless), B = g_rpn_conv1 (pre-rounded).
// Bias + paired softmax (c, c+9) for cls, bias for box, two zero scalars.
// Cs (64x132) reuses stage 0/1 smem after the mainloop (stage 2 untouched).
// ---------------------------------------------------------------------------
#define HD_A_ST 2304                    // 64*36
#define HD_B_ST 4352                    // 32*136
#define HD_STAGE (HD_A_ST + HD_B_ST)    // 6656 floats
#define HD_SMEM (3 * HD_STAGE * 4)      // 79872 bytes

__global__ __launch_bounds__(256, 2)
void k_head(const float* __restrict__ b_cls, const float* __restrict__ b_box,
            float* __restrict__ out)
{
    extern __shared__ float ds[];
    const int n  = blockIdx.z;
    const int n0 = blockIdx.x * 128;
    const float* Bp = g_rpn_conv1 + (size_t)n * 384 * HW + n0;

    const int tid  = threadIdx.x;
    const int warp = tid >> 5, lane = tid & 31;
    const int wm = (warp >> 2) * 32, wn = (warp & 3) * 32;
    const int g  = lane >> 2, t4 = lane & 3;

    auto loadT = [&](int t) {
        float* As = ds + (t % 3) * HD_STAGE;
        float* Bs = As + HD_A_ST;
        const int k0 = t * 32;
        #pragma unroll
        for (int j = 0; j < 2; j++) {
            int e = tid + j * 256;                // 0..511
            cp16(sptr(As + (e >> 3) * 36 + (e & 7) * 4),
                 g_wh + (size_t)(e >> 3) * 384 + k0 + (e & 7) * 4, true);
        }
        #pragma unroll
        for (int j = 0; j < 4; j++) {
            int e = tid + j * 256;                // 0..1023
            cp16(sptr(Bs + (e >> 5) * 136 + (e & 31) * 4),
                 Bp + (size_t)(k0 + (e >> 5)) * HW + (e & 31) * 4, true);
        }
        cpcommit();
    };

    float acc[2][4][4] = {};

    loadT(0);
    loadT(1);
    for (int t = 0; t < 12; t++) {
        if (t < 11) cpwait1(); else cpwait0();
        __syncthreads();
        if (t + 2 < 12) loadT(t + 2);

        const float* As = ds + (t % 3) * HD_STAGE;
        const float* Bs = As + HD_A_ST;
        #pragma unroll
        for (int ks = 0; ks < 4; ks++) {
            const int kk = ks * 8;
            unsigned a[2][4], b[4][2];
            #pragma unroll
            for (int mf = 0; mf < 2; mf++) {
                int r = wm + mf * 16;
                a[mf][0] = __float_as_uint(As[(r + g) * 36 + kk + t4]);
                a[mf][1] = __float_as_uint(As[(r + g + 8) * 36 + kk + t4]);
                a[mf][2] = __float_as_uint(As[(r + g) * 36 + kk + t4 + 4]);
                a[mf][3] = __float_as_uint(As[(r + g + 8) * 36 + kk + t4 + 4]);
            }
            #pragma unroll
            for (int nf = 0; nf < 4; nf++) {
                int c = wn + nf * 8 + g;
                b[nf][0] = __float_as_uint(Bs[(kk + t4) * 136 + c]);
                b[nf][1] = __float_as_uint(Bs[(kk + t4 + 4) * 136 + c]);
            }
            #pragma unroll
            for (int mf = 0; mf < 2; mf++)
                #pragma unroll
                for (int nf = 0; nf < 4; nf++)
                    mma8(acc[mf][nf], a[mf], b[nf]);
        }
    }

    // Park scores in smem. Cs occupies stages 0/1 region; last compute read
    // only stage 2 (t=11 -> 11%3=2), so no sync needed before these writes.
    float (*Cs)[132] = (float(*)[132])ds;
    #pragma unroll
    for (int mf = 0; mf < 2; mf++) {
        int r0 = wm + mf * 16 + g;
        #pragma unroll
        for (int nf = 0; nf < 4; nf++) {
            int c = wn + nf * 8 + t4 * 2;
            Cs[r0][c]         = acc[mf][nf][0];
            Cs[r0][c + 1]     = acc[mf][nf][1];
            Cs[r0 + 8][c]     = acc[mf][nf][2];
            Cs[r0 + 8][c + 1] = acc[mf][nf][3];
        }
    }
    __syncthreads();

    const size_t F1 = (size_t)CB * CIN * HW;
    const size_t F2 = F1 + (size_t)CB * 18 * HW;
    const size_t F3 = F2 + (size_t)CB * 36 * HW;

    for (int it = tid; it < 9 * 128; it += 256) {
        int c = it >> 7, j = it & 127;
        float s0 = Cs[c][j]     + b_cls[c];
        float s1 = Cs[c + 9][j] + b_cls[c + 9];
        float m  = fmaxf(s0, s1);
        float e0 = expf(s0 - m), e1 = expf(s1 - m);
        float inv = 1.f / (e0 + e1);
        out[F1 + (size_t)n * 18 * HW + (size_t)c * HW + n0 + j]       = e0 * inv;
        out[F1 + (size_t)n * 18 * HW + (size_t)(c + 9) * HW + n0 + j] = e1 * inv;
    }
    for (int it = tid; it < 36 * 128; it += 256) {
        int c = it >> 7, j = it & 127;
        out[F2 + (size_t)n * 36 * HW + (size_t)c * HW + n0 + j] = Cs[18 + c][j] + b_box[c];
    }
    if (n == 0 && blockIdx.x == 0 && tid == 0) {
        out[F3]     = 0.f;
        out[F3 + 1] = 0.f;
    }
}

// ---------------------------------------------------------------------------
extern "C" void kernel_launch(void* const* d_in, const int* in_sizes, int n_in,
                              void* d_out, int out_size)
{
    const float* base  = (const float*)d_in[0];
    const float* w_f   = (const float*)d_in[3];
    const float* b_f   = (const float*)d_in[4];
    const float* w_2   = (const float*)d_in[5];
    const float* b_2   = (const float*)d_in[6];
    const float* w_c1  = (const float*)d_in[7];
    const float* b_c1  = (const float*)d_in[8];
    const float* w_cls = (const float*)d_in[9];
    const float* b_cls = (const float*)d_in[10];
    const float* w_box = (const float*)d_in[11];
    const float* b_box = (const float*)d_in[12];
    float* out = (float*)d_out;

    static bool attr_set = false;
    if (!attr_set) {
        cudaFuncSetAttribute(k_conv1, cudaFuncAttributeMaxDynamicSharedMemorySize, C1_SMEM);
        cudaFuncSetAttribute(k_conv3, cudaFuncAttributeMaxDynamicSharedMemorySize, C3_SMEM);
        cudaFuncSetAttribute(k_head,  cudaFuncAttributeMaxDynamicSharedMemorySize, HD_SMEM);
        attr_set = true;
    }

    dim3 blk(256);
    k_prep <<<(PREP_TOT + 255) / 256, blk>>>(w_f, w_2, w_c1, w_cls, w_box);
    k_conv1<<<dim3(32, 4, CB), blk, C1_SMEM>>>(base, b_f, b_2, out);
    k_conv3<<<dim3(32, 3, CB), blk, C3_SMEM>>>(b_c1);
    k_head <<<dim3(32, 1, CB), blk, HD_SMEM>>>(b_cls, b_box, out);
}

// round 9
// speedup vs baseline: 1.6043x; 1.1277x over previous
#include <cuda_runtime.h>
#include <cstdint>

// Problem constants
#define CB   8
#define HW   4096          // 64*64
#define CIN  512

// Device scratch (allowed: __device__ globals)
static __device__ float g_rpn_conv1[(size_t)CB * 384 * HW]; // conv3 out (rounded)
static __device__ float g_featr[(size_t)CB * 128 * HW];     // rounded convf_rpn
static __device__ float g_wa[512 * 512];                    // rounded [w_f; w_2]
static __device__ float g_wt[9 * 384 * 128];                // rounded w_c1, tap-major
static __device__ float g_wh[64 * 384];                     // rounded [w_cls; w_box; 0]

// ---------------------------------------------------------------------------
// helpers
// ---------------------------------------------------------------------------
__device__ __forceinline__ unsigned f2tf(float x) {
    unsigned r;
    asm("cvt.rna.tf32.f32 %0, %1;" : "=r"(r) : "f"(x));
    return r;
}
__device__ __forceinline__ float rndf(float x) { return __uint_as_float(f2tf(x)); }

__device__ __forceinline__ void mma8(float d[4], const unsigned a[4], const unsigned b[2]) {
    asm volatile(
        "mma.sync.aligned.m16n8k8.row.col.f32.tf32.tf32.f32 "
        "{%0,%1,%2,%3}, {%4,%5,%6,%7}, {%8,%9}, {%0,%1,%2,%3};\n"
        : "+f"(d[0]), "+f"(d[1]), "+f"(d[2]), "+f"(d[3])
        : "r"(a[0]), "r"(a[1]), "r"(a[2]), "r"(a[3]), "r"(b[0]), "r"(b[1]));
}

__device__ __forceinline__ unsigned sptr(const void* p) {
    return (unsigned)__cvta_generic_to_shared(p);
}
__device__ __forceinline__ void cp16(unsigned d, const void* s, bool ok) {
    asm volatile("cp.async.cg.shared.global [%0], [%1], 16, %2;\n"
                 :: "r"(d), "l"(s), "r"(ok ? 16 : 0));
}
__device__ __forceinline__ void cpcommit() { asm volatile("cp.async.commit_group;\n"); }
__device__ __forceinline__ void cpwait1()  { asm volatile("cp.async.wait_group 1;\n"); }
__device__ __forceinline__ void cpwait0()  { asm volatile("cp.async.wait_group 0;\n"); }

// ---------------------------------------------------------------------------
// Prep kernel: round weights to tf32 once; transpose w_c1 to tap-major.
// ---------------------------------------------------------------------------
#define PREP_N1 262144              // 512*512
#define PREP_N2 442368              // 9*384*128
#define PREP_N3 24576               // 64*384
#define PREP_TOT (PREP_N1 + PREP_N2 + PREP_N3)

__global__ void k_prep(const float* __restrict__ w_f, const float* __restrict__ w_2,
                       const float* __restrict__ w_c1,
                       const float* __restrict__ w_cls, const float* __restrict__ w_box)
{
    int i = blockIdx.x * 256 + threadIdx.x;
    if (i < PREP_N1) {
        int m = i >> 9;
        float v = (m < 128) ? w_f[i] : w_2[i - 65536];
        g_wa[i] = rndf(v);
        return;
    }
    i -= PREP_N1;
    if (i < PREP_N2) {
        int tap = i / 49152, rem = i % 49152;
        int m = rem >> 7, c = rem & 127;
        g_wt[i] = rndf(w_c1[(size_t)m * 1152 + c * 9 + tap]);
        return;
    }
    i -= PREP_N2;
    if (i < PREP_N3) {
        int r = i / 384, k = i - r * 384;
        float v;
        if (r < 18)      v = w_cls[i];
        else if (r < 54) v = w_box[(r - 18) * 384 + k];
        else             v = 0.f;
        g_wh[i] = rndf(v);
    }
}

// ---------------------------------------------------------------------------
// Kernel 1: fused 1x1 conv 512 -> 512, ReLU -> d_out feat region.
// Block 128x128, 4 warps of 64x64 (2M x 2N), 128 threads. K-tile 16,
// 3-stage cp.async ring, one __syncthreads per iteration.
// Warp-tile 64x64 halves smem crossbar bytes per MMA vs 64x32.
// mt==0 also writes rounded channels 0..127 to g_featr for conv3.
// ---------------------------------------------------------------------------
#define C1_A_ST (128 * 20)              // 2560 floats
#define C1_B_ST (16 * 136)              // 2176 floats
#define C1_STAGE (C1_A_ST + C1_B_ST)    // 4736 floats
#define C1_SMEM (3 * C1_STAGE * 4)      // 56832 bytes

__global__ __launch_bounds__(128, 2)
void k_conv1(const float* __restrict__ base_feat,
             const float* __restrict__ b_f, const float* __restrict__ b_2,
             float* __restrict__ out)
{
    extern __shared__ float ds[];
    const int n  = blockIdx.z;
    const int mt = blockIdx.y;
    const int n0 = blockIdx.x * 128;
    const float* A  = g_wa + (size_t)mt * 128 * CIN;
    const float* bi = (mt == 0) ? b_f : (b_2 + (mt - 1) * 128);
    const float* Bp = base_feat + (size_t)n * CIN * HW + n0;

    const int tid  = threadIdx.x;
    const int warp = tid >> 5, lane = tid & 31;
    const int wm = (warp >> 1) * 64, wn = (warp & 1) * 64;
    const int g  = lane >> 2, t4 = lane & 3;

    auto loadT = [&](int t) {
        float* As = ds + (t % 3) * C1_STAGE;
        float* Bs = As + C1_A_ST;
        const int k0 = t * 16;
        #pragma unroll
        for (int j = 0; j < 4; j++) {
            int e = tid + j * 128;                // 0..511
            cp16(sptr(As + (e >> 2) * 20 + (e & 3) * 4),
                 A + (size_t)(e >> 2) * CIN + k0 + (e & 3) * 4, true);
            cp16(sptr(Bs + (e >> 5) * 136 + (e & 31) * 4),
                 Bp + (size_t)(k0 + (e >> 5)) * HW + (e & 31) * 4, true);
        }
        cpcommit();
    };

    float acc[4][8][4] = {};

    loadT(0);
    loadT(1);
    for (int t = 0; t < 32; t++) {
        if (t < 31) cpwait1(); else cpwait0();
        __syncthreads();
        if (t + 2 < 32) loadT(t + 2);

        const float* As = ds + (t % 3) * C1_STAGE;
        const float* Bs = As + C1_A_ST;
        #pragma unroll
        for (int ks = 0; ks < 2; ks++) {
            const int kk = ks * 8;
            unsigned a[4][4], b[8][2];
            #pragma unroll
            for (int mf = 0; mf < 4; mf++) {
                int r = wm + mf * 16;
                a[mf][0] = __float_as_uint(As[(r + g) * 20 + kk + t4]);
                a[mf][1] = __float_as_uint(As[(r + g + 8) * 20 + kk + t4]);
                a[mf][2] = __float_as_uint(As[(r + g) * 20 + kk + t4 + 4]);
                a[mf][3] = __float_as_uint(As[(r + g + 8) * 20 + kk + t4 + 4]);
            }
            #pragma unroll
            for (int nf = 0; nf < 8; nf++) {
                int c = wn + nf * 8 + g;
                b[nf][0] = f2tf(Bs[(kk + t4) * 136 + c]);
                b[nf][1] = f2tf(Bs[(kk + t4 + 4) * 136 + c]);
            }
            #pragma unroll
            for (int mf = 0; mf < 4; mf++)
                #pragma unroll
                for (int nf = 0; nf < 8; nf++)
                    mma8(acc[mf][nf], a[mf], b[nf]);
        }
    }

    float* outb = out + (size_t)n * CIN * HW + (size_t)mt * 128 * HW;
    float* fr   = g_featr + (size_t)n * 128 * HW;
    #pragma unroll
    for (int mf = 0; mf < 4; mf++) {
        int r0 = wm + mf * 16 + g;
        float bv0 = bi[r0], bv1 = bi[r0 + 8];
        #pragma unroll
        for (int nf = 0; nf < 8; nf++) {
            int c = n0 + wn + nf * 8 + t4 * 2;
            float2 v0, v1;
            v0.x = fmaxf(acc[mf][nf][0] + bv0, 0.f);
            v0.y = fmaxf(acc[mf][nf][1] + bv0, 0.f);
            v1.x = fmaxf(acc[mf][nf][2] + bv1, 0.f);
            v1.y = fmaxf(acc[mf][nf][3] + bv1, 0.f);
            *(float2*)(outb + (size_t)r0 * HW + c)       = v0;
            *(float2*)(outb + (size_t)(r0 + 8) * HW + c) = v1;
            if (mt == 0) {
                float2 r2a, r2b;
                r2a.x = rndf(v0.x); r2a.y = rndf(v0.y);
                r2b.x = rndf(v1.x); r2b.y = rndf(v1.y);
                *(float2*)(fr + (size_t)r0 * HW + c)       = r2a;
                *(float2*)(fr + (size_t)(r0 + 8) * HW + c) = r2b;
            }
        }
    }
}

// ---------------------------------------------------------------------------
// Kernel 2: 3x3 conv 128 -> 384 pad=1, ReLU -> g_rpn_conv1 (rounded).
// Block 128x128, 4 warps of 64x64, 128 threads. Pre-rounded inputs -> no cvt,
// no edge masking. A: 3-stage ring over (kc,tap) iterations; H: 2 buffers at
// kc cadence. One __syncthreads per iteration. H slice: [8 zero pad][4 rows
// of 68], cols 64..67 zeroed.
// ---------------------------------------------------------------------------
#define H_ROW   68
#define H_PAD   8
#define H_SLICE 280                 // 8 pad + 4*68
#define H_BUFN  (16 * H_SLICE)      // 4480 floats per buffer
#define C3_AS_F (3 * 128 * 20)      // 7680 floats (3 stages)
#define C3_SMEM ((C3_AS_F + 2 * H_BUFN) * 4)   // 66560 bytes

__global__ __launch_bounds__(128, 2)
void k_conv3(const float* __restrict__ b_c1)
{
    extern __shared__ float ds[];
    float* Asb = ds;                 // 3 stages of [128][20]
    float* Hb  = ds + C3_AS_F;

    const int n  = blockIdx.z;
    const int m0 = blockIdx.y * 128;
    const int n0 = blockIdx.x * 128;
    const int y0 = blockIdx.x * 2;
    const float* In = g_featr + (size_t)n * 128 * HW;

    const int tid  = threadIdx.x;
    const int warp = tid >> 5, lane = tid & 31;
    const int wm = (warp >> 1) * 64, wn = (warp & 1) * 64;
    const int g  = lane >> 2, t4 = lane & 3;

    // zero pads: per (buf,k): front pad [0..7] + halo cols 64..67 of 4 rows
    for (int i = tid; i < 768; i += 128) {
        int buf = i / 384, r2 = i % 384;
        int k = r2 / 24, e = r2 % 24;
        int off;
        if (e < 8) off = e;
        else { int rr = (e - 8) >> 2, cc = (e - 8) & 3;
               off = H_PAD + rr * H_ROW + 64 + cc; }
        Hb[buf * H_BUFN + k * H_SLICE + off] = 0.f;
    }

    auto loadA = [&](int t) {                     // t = iteration index
        int kc = t / 9, tap = t - kc * 9;
        float* As = Asb + (t % 3) * (128 * 20);
        #pragma unroll
        for (int j = 0; j < 4; j++) {
            int e = tid + j * 128;                 // 0..511
            int row = e >> 2, u = e & 3;
            cp16(sptr(As + row * 20 + u * 4),
                 g_wt + ((size_t)tap * 384 + m0 + row) * 128 + kc * 16 + u * 4, true);
        }
    };
    auto loadH = [&](int kc, int buf) {
        #pragma unroll
        for (int j = 0; j < 8; j++) {
            int e = tid + j * 128;                 // 0..1023
            int k = e >> 6, rem = e & 63, r = rem >> 4, xu = rem & 15;
            int gy = y0 - 1 + r;
            cp16(sptr(&Hb[buf * H_BUFN + k * H_SLICE + H_PAD + r * H_ROW + xu * 4]),
                 In + (size_t)(kc * 16 + k) * HW + gy * 64 + xu * 4,
                 (unsigned)gy < 64u);
        }
    };

    // per-thread pixel base offsets into an H slice (center row = 1 + px>>6)
    int ib[8];
    #pragma unroll
    for (int nf = 0; nf < 8; nf++) {
        int px = wn + nf * 8 + g;
        ib[nf] = H_PAD + (1 + (px >> 6)) * H_ROW + (px & 63);
    }

    float acc[4][8][4] = {};

    // prologue: g0 = {A(0), H(0)}, g1 = {A(1)}
    loadA(0); loadH(0, 0); cpcommit();
    loadA(1); cpcommit();

    for (int it = 0; it < 72; it++) {
        const int kc = it / 9, tap = it - kc * 9;
        if (it < 71) cpwait1(); else cpwait0();
        __syncthreads();
        if (it + 2 < 72) {
            loadA(it + 2);
            if (tap == 0 && kc < 7) loadH(kc + 1, (kc + 1) & 1);
            cpcommit();
        }

        const int dy = tap / 3 - 1, dx = tap % 3 - 1;
        const int hoff = dy * H_ROW + dx;
        const float* As = Asb + (it % 3) * (128 * 20);
        const float* Hc = Hb + (kc & 1) * H_BUFN;

        #pragma unroll
        for (int ks = 0; ks < 2; ks++) {
            const int kk = ks * 8;
            unsigned a[4][4], b[8][2];
            #pragma unroll
            for (int mf = 0; mf < 4; mf++) {
                int r = wm + mf * 16;
                a[mf][0] = __float_as_uint(As[(r + g) * 20 + kk + t4]);
                a[mf][1] = __float_as_uint(As[(r + g + 8) * 20 + kk + t4]);
                a[mf][2] = __float_as_uint(As[(r + g) * 20 + kk + t4 + 4]);
                a[mf][3] = __float_as_uint(As[(r + g + 8) * 20 + kk + t4 + 4]);
            }
            #pragma unroll
            for (int nf = 0; nf < 8; nf++) {
                b[nf][0] = __float_as_uint(Hc[(kk + t4) * H_SLICE + ib[nf] + hoff]);
                b[nf][1] = __float_as_uint(Hc[(kk + t4 + 4) * H_SLICE + ib[nf] + hoff]);
            }
            #pragma unroll
            for (int mf = 0; mf < 4; mf++)
                #pragma unroll
                for (int nf = 0; nf < 8; nf++)
                    mma8(acc[mf][nf], a[mf], b[nf]);
        }
    }

    float* ob = g_rpn_conv1 + (size_t)n * 384 * HW;
    #pragma unroll
    for (int mf = 0; mf < 4; mf++) {
        int r0 = m0 + wm + mf * 16 + g;
        float bv0 = b_c1[r0], bv1 = b_c1[r0 + 8];
        #pragma unroll
        for (int nf = 0; nf < 8; nf++) {
            int c = n0 + wn + nf * 8 + t4 * 2;
            float2 v0, v1;
            v0.x = rndf(fmaxf(acc[mf][nf][0] + bv0, 0.f));
            v0.y = rndf(fmaxf(acc[mf][nf][1] + bv0, 0.f));
            v1.x = rndf(fmaxf(acc[mf][nf][2] + bv1, 0.f));
            v1.y = rndf(fmaxf(acc[mf][nf][3] + bv1, 0.f));
            *(float2*)(ob + (size_t)r0 * HW + c)       = v0;
            *(float2*)(ob + (size_t)(r0 + 8) * HW + c) = v1;
        }
    }
}

// ---------------------------------------------------------------------------
// Kernel 3: head. 3-stage ring, K-tile 32, one sync per iteration (as R8).
// A = g_wh (pre-rounded, branchless), B = g_rpn_conv1 (pre-rounded).
// Bias + paired softmax (c, c+9) for cls, bias for box, two zero scalars.
// ---------------------------------------------------------------------------
#define HD_A_ST 2304                    // 64*36
#define HD_B_ST 4352                    // 32*136
#define HD_STAGE (HD_A_ST + HD_B_ST)    // 6656 floats
#define HD_SMEM (3 * HD_STAGE * 4)      // 79872 bytes

__global__ __launch_bounds__(256, 2)
void k_head(const float* __restrict__ b_cls, const float* __restrict__ b_box,
            float* __restrict__ out)
{
    extern __shared__ float ds[];
    const int n  = blockIdx.z;
    const int n0 = blockIdx.x * 128;
    const float* Bp = g_rpn_conv1 + (size_t)n * 384 * HW + n0;

    const int tid  = threadIdx.x;
    const int warp = tid >> 5, lane = tid & 31;
    const int wm = (warp >> 2) * 32, wn = (warp & 3) * 32;
    const int g  = lane >> 2, t4 = lane & 3;

    auto loadT = [&](int t) {
        float* As = ds + (t % 3) * HD_STAGE;
        float* Bs = As + HD_A_ST;
        const int k0 = t * 32;
        #pragma unroll
        for (int j = 0; j < 2; j++) {
            int e = tid + j * 256;                // 0..511
            cp16(sptr(As + (e >> 3) * 36 + (e & 7) * 4),
                 g_wh + (size_t)(e >> 3) * 384 + k0 + (e & 7) * 4, true);
        }
        #pragma unroll
        for (int j = 0; j < 4; j++) {
            int e = tid + j * 256;                // 0..1023
            cp16(sptr(Bs + (e >> 5) * 136 + (e & 31) * 4),
                 Bp + (size_t)(k0 + (e >> 5)) * HW + (e & 31) * 4, true);
        }
        cpcommit();
    };

    float acc[2][4][4] = {};

    loadT(0);
    loadT(1);
    for (int t = 0; t < 12; t++) {
        if (t < 11) cpwait1(); else cpwait0();
        __syncthreads();
        if (t + 2 < 12) loadT(t + 2);

        const float* As = ds + (t % 3) * HD_STAGE;
        const float* Bs = As + HD_A_ST;
        #pragma unroll
        for (int ks = 0; ks < 4; ks++) {
            const int kk = ks * 8;
            unsigned a[2][4], b[4][2];
            #pragma unroll
            for (int mf = 0; mf < 2; mf++) {
                int r = wm + mf * 16;
                a[mf][0] = __float_as_uint(As[(r + g) * 36 + kk + t4]);
                a[mf][1] = __float_as_uint(As[(r + g + 8) * 36 + kk + t4]);
                a[mf][2] = __float_as_uint(As[(r + g) * 36 + kk + t4 + 4]);
                a[mf][3] = __float_as_uint(As[(r + g + 8) * 36 + kk + t4 + 4]);
            }
            #pragma unroll
            for (int nf = 0; nf < 4; nf++) {
                int c = wn + nf * 8 + g;
                b[nf][0] = __float_as_uint(Bs[(kk + t4) * 136 + c]);
                b[nf][1] = __float_as_uint(Bs[(kk + t4 + 4) * 136 + c]);
            }
            #pragma unroll
            for (int mf = 0; mf < 2; mf++)
                #pragma unroll
                for (int nf = 0; nf < 4; nf++)
                    mma8(acc[mf][nf], a[mf], b[nf]);
        }
    }

    // Park scores in smem. Cs occupies stages 0/1 region; last compute read
    // only stage 2 (t=11 -> 11%3=2), so no sync needed before these writes.
    float (*Cs)[132] = (float(*)[132])ds;
    #pragma unroll
    for (int mf = 0; mf < 2; mf++) {
        int r0 = wm + mf * 16 + g;
        #pragma unroll
        for (int nf = 0; nf < 4; nf++) {
            int c = wn + nf * 8 + t4 * 2;
            Cs[r0][c]         = acc[mf][nf][0];
            Cs[r0][c + 1]     = acc[mf][nf][1];
            Cs[r0 + 8][c]     = acc[mf][nf][2];
            Cs[r0 + 8][c + 1] = acc[mf][nf][3];
        }
    }
    __syncthreads();

    const size_t F1 = (size_t)CB * CIN * HW;
    const size_t F2 = F1 + (size_t)CB * 18 * HW;
    const size_t F3 = F2 + (size_t)CB * 36 * HW;

    for (int it = tid; it < 9 * 128; it += 256) {
        int c = it >> 7, j = it & 127;
        float s0 = Cs[c][j]     + b_cls[c];
        float s1 = Cs[c + 9][j] + b_cls[c + 9];
        float m  = fmaxf(s0, s1);
        float e0 = expf(s0 - m), e1 = expf(s1 - m);
        float inv = 1.f / (e0 + e1);
        out[F1 + (size_t)n * 18 * HW + (size_t)c * HW + n0 + j]       = e0 * inv;
        out[F1 + (size_t)n * 18 * HW + (size_t)(c + 9) * HW + n0 + j] = e1 * inv;
    }
    for (int it = tid; it < 36 * 128; it += 256) {
        int c = it >> 7, j = it & 127;
        out[F2 + (size_t)n * 36 * HW + (size_t)c * HW + n0 + j] = Cs[18 + c][j] + b_box[c];
    }
    if (n == 0 && blockIdx.x == 0 && tid == 0) {
        out[F3]     = 0.f;
        out[F3 + 1] = 0.f;
    }
}

// ---------------------------------------------------------------------------
extern "C" void kernel_launch(void* const* d_in, const int* in_sizes, int n_in,
                              void* d_out, int out_size)
{
    const float* base  = (const float*)d_in[0];
    const float* w_f   = (const float*)d_in[3];
    const float* b_f   = (const float*)d_in[4];
    const float* w_2   = (const float*)d_in[5];
    const float* b_2   = (const float*)d_in[6];
    const float* w_c1  = (const float*)d_in[7];
    const float* b_c1  = (const float*)d_in[8];
    const float* w_cls = (const float*)d_in[9];
    const float* b_cls = (const float*)d_in[10];
    const float* w_box = (const float*)d_in[11];
    const float* b_box = (const float*)d_in[12];
    float* out = (float*)d_out;

    static bool attr_set = false;
    if (!attr_set) {
        cudaFuncSetAttribute(k_conv1, cudaFuncAttributeMaxDynamicSharedMemorySize, C1_SMEM);
        cudaFuncSetAttribute(k_conv3, cudaFuncAttributeMaxDynamicSharedMemorySize, C3_SMEM);
        cudaFuncSetAttribute(k_head,  cudaFuncAttributeMaxDynamicSharedMemorySize, HD_SMEM);
        attr_set = true;
    }

    k_prep <<<(PREP_TOT + 255) / 256, 256>>>(w_f, w_2, w_c1, w_cls, w_box);
    k_conv1<<<dim3(32, 4, CB), 128, C1_SMEM>>>(base, b_f, b_2, out);
    k_conv3<<<dim3(32, 3, CB), 128, C3_SMEM>>>(b_c1);
    k_head <<<dim3(32, 1, CB), 256, HD_SMEM>>>(b_cls, b_box, out);
}

// round 10
// speedup vs baseline: 1.7169x; 1.0702x over previous
#include <cuda_runtime.h>
#include <cstdint>

// Problem constants
#define CB   8
#define HW   4096          // 64*64
#define CIN  512

// Device scratch (allowed: __device__ globals)
static __device__ float g_rpn_conv1[(size_t)CB * 384 * HW]; // conv3 out (rounded)
static __device__ float g_featr[(size_t)CB * 128 * HW];     // rounded convf_rpn
static __device__ float g_wa[512 * 512];                    // rounded [w_f; w_2]
static __device__ float g_wt[9 * 384 * 128];                // rounded w_c1, tap-major
static __device__ float g_wh[64 * 384];                     // rounded [w_cls; w_box; 0]

// ---------------------------------------------------------------------------
// helpers
// ---------------------------------------------------------------------------
__device__ __forceinline__ unsigned f2tf(float x) {
    unsigned r;
    asm("cvt.rna.tf32.f32 %0, %1;" : "=r"(r) : "f"(x));
    return r;
}
__device__ __forceinline__ float rndf(float x) { return __uint_as_float(f2tf(x)); }

__device__ __forceinline__ void mma8(float d[4], const unsigned a[4], const unsigned b[2]) {
    asm volatile(
        "mma.sync.aligned.m16n8k8.row.col.f32.tf32.tf32.f32 "
        "{%0,%1,%2,%3}, {%4,%5,%6,%7}, {%8,%9}, {%0,%1,%2,%3};\n"
        : "+f"(d[0]), "+f"(d[1]), "+f"(d[2]), "+f"(d[3])
        : "r"(a[0]), "r"(a[1]), "r"(a[2]), "r"(a[3]), "r"(b[0]), "r"(b[1]));
}

__device__ __forceinline__ unsigned sptr(const void* p) {
    return (unsigned)__cvta_generic_to_shared(p);
}
__device__ __forceinline__ void cp16(unsigned d, const void* s, bool ok) {
    asm volatile("cp.async.cg.shared.global [%0], [%1], 16, %2;\n"
                 :: "r"(d), "l"(s), "r"(ok ? 16 : 0));
}
__device__ __forceinline__ void cpcommit() { asm volatile("cp.async.commit_group;\n"); }
__device__ __forceinline__ void cpwait2()  { asm volatile("cp.async.wait_group 2;\n"); }
__device__ __forceinline__ void cpwait1()  { asm volatile("cp.async.wait_group 1;\n"); }

// ---------------------------------------------------------------------------
// Prep kernel: round weights to tf32 once; transpose w_c1 to tap-major.
// ---------------------------------------------------------------------------
#define PREP_N1 262144              // 512*512
#define PREP_N2 442368              // 9*384*128
#define PREP_N3 24576               // 64*384
#define PREP_TOT (PREP_N1 + PREP_N2 + PREP_N3)

__global__ void k_prep(const float* __restrict__ w_f, const float* __restrict__ w_2,
                       const float* __restrict__ w_c1,
                       const float* __restrict__ w_cls, const float* __restrict__ w_box)
{
    int i = blockIdx.x * 256 + threadIdx.x;
    if (i < PREP_N1) {
        int m = i >> 9;
        float v = (m < 128) ? w_f[i] : w_2[i - 65536];
        g_wa[i] = rndf(v);
        return;
    }
    i -= PREP_N1;
    if (i < PREP_N2) {
        int tap = i / 49152, rem = i % 49152;
        int m = rem >> 7, c = rem & 127;
        g_wt[i] = rndf(w_c1[(size_t)m * 1152 + c * 9 + tap]);
        return;
    }
    i -= PREP_N2;
    if (i < PREP_N3) {
        int r = i / 384, k = i - r * 384;
        float v;
        if (r < 18)      v = w_cls[i];
        else if (r < 54) v = w_box[(r - 18) * 384 + k];
        else             v = 0.f;
        g_wh[i] = rndf(v);
    }
}

// ---------------------------------------------------------------------------
// Kernel 1: fused 1x1 conv 512 -> 512, ReLU -> d_out feat region.
// Block 128x128, 4 warps of 64x64, 128 threads. K-tile 16, 4-stage cp.async
// ring (1 commit + 1 wait_group(1) per iter => stages t AND t+1 valid at top
// of iter t). Register fragment pipeline: Fa holds ks0 frags preloaded from
// the PREVIOUS iteration; per iter: load Fb(ks1) || mma(Fa) || prefetch
// Fa(ks0 of t+1) || mma(Fb). No LDS latency exposed at iteration entry.
// mt==0 also writes rounded channels 0..127 to g_featr for conv3.
// ---------------------------------------------------------------------------
#define C1_A_ST (128 * 20)              // 2560 floats
#define C1_B_ST (16 * 136)              // 2176 floats
#define C1_STAGE (C1_A_ST + C1_B_ST)    // 4736 floats
#define C1_SMEM (4 * C1_STAGE * 4)      // 75776 bytes

__global__ __launch_bounds__(128, 2)
void k_conv1(const float* __restrict__ base_feat,
             const float* __restrict__ b_f, const float* __restrict__ b_2,
             float* __restrict__ out)
{
    extern __shared__ float ds[];
    const int n  = blockIdx.z;
    const int mt = blockIdx.y;
    const int n0 = blockIdx.x * 128;
    const float* A  = g_wa + (size_t)mt * 128 * CIN;
    const float* bi = (mt == 0) ? b_f : (b_2 + (mt - 1) * 128);
    const float* Bp = base_feat + (size_t)n * CIN * HW + n0;

    const int tid  = threadIdx.x;
    const int warp = tid >> 5, lane = tid & 31;
    const int wm = (warp >> 1) * 64, wn = (warp & 1) * 64;
    const int g  = lane >> 2, t4 = lane & 3;

    auto loadT = [&](int t) {
        float* As = ds + (t & 3) * C1_STAGE;
        float* Bs = As + C1_A_ST;
        const int k0 = t * 16;
        #pragma unroll
        for (int j = 0; j < 4; j++) {
            int e = tid + j * 128;                // 0..511
            cp16(sptr(As + (e >> 2) * 20 + (e & 3) * 4),
                 A + (size_t)(e >> 2) * CIN + k0 + (e & 3) * 4, true);
            cp16(sptr(Bs + (e >> 5) * 136 + (e & 31) * 4),
                 Bp + (size_t)(k0 + (e >> 5)) * HW + (e & 31) * 4, true);
        }
        cpcommit();
    };

    auto ldfrag = [&](const float* As, const float* Bs, int kk,
                      unsigned (&a)[4][4], unsigned (&b)[8][2]) {
        #pragma unroll
        for (int mf = 0; mf < 4; mf++) {
            int r = wm + mf * 16;
            a[mf][0] = __float_as_uint(As[(r + g) * 20 + kk + t4]);
            a[mf][1] = __float_as_uint(As[(r + g + 8) * 20 + kk + t4]);
            a[mf][2] = __float_as_uint(As[(r + g) * 20 + kk + t4 + 4]);
            a[mf][3] = __float_as_uint(As[(r + g + 8) * 20 + kk + t4 + 4]);
        }
        #pragma unroll
        for (int nf = 0; nf < 8; nf++) {
            int c = wn + nf * 8 + g;
            b[nf][0] = f2tf(Bs[(kk + t4) * 136 + c]);
            b[nf][1] = f2tf(Bs[(kk + t4 + 4) * 136 + c]);
        }
    };

    float acc[4][8][4] = {};
    unsigned aA[4][4], bA[8][2], aB[4][4], bB[8][2];

    loadT(0); loadT(1); loadT(2);
    cpwait2();
    __syncthreads();
    ldfrag(ds, ds + C1_A_ST, 0, aA, bA);           // ks0 of t=0

    for (int t = 0; t < 32; t++) {
        cpwait1();                                 // stages <= t+1 complete
        __syncthreads();                           // ... and CTA-visible
        if (t + 3 < 32) loadT(t + 3); else cpcommit();

        const float* As = ds + (t & 3) * C1_STAGE;
        ldfrag(As, As + C1_A_ST, 8, aB, bB);       // ks1 of t
        #pragma unroll
        for (int mf = 0; mf < 4; mf++)
            #pragma unroll
            for (int nf = 0; nf < 8; nf++)
                mma8(acc[mf][nf], aA[mf], bA[nf]);
        if (t + 1 < 32) {
            const float* As2 = ds + ((t + 1) & 3) * C1_STAGE;
            ldfrag(As2, As2 + C1_A_ST, 0, aA, bA); // ks0 of t+1 (stage valid)
        }
        #pragma unroll
        for (int mf = 0; mf < 4; mf++)
            #pragma unroll
            for (int nf = 0; nf < 8; nf++)
                mma8(acc[mf][nf], aB[mf], bB[nf]);
    }

    float* outb = out + (size_t)n * CIN * HW + (size_t)mt * 128 * HW;
    float* fr   = g_featr + (size_t)n * 128 * HW;
    #pragma unroll
    for (int mf = 0; mf < 4; mf++) {
        int r0 = wm + mf * 16 + g;
        float bv0 = bi[r0], bv1 = bi[r0 + 8];
        #pragma unroll
        for (int nf = 0; nf < 8; nf++) {
            int c = n0 + wn + nf * 8 + t4 * 2;
            float2 v0, v1;
            v0.x = fmaxf(acc[mf][nf][0] + bv0, 0.f);
            v0.y = fmaxf(acc[mf][nf][1] + bv0, 0.f);
            v1.x = fmaxf(acc[mf][nf][2] + bv1, 0.f);
            v1.y = fmaxf(acc[mf][nf][3] + bv1, 0.f);
            *(float2*)(outb + (size_t)r0 * HW + c)       = v0;
            *(float2*)(outb + (size_t)(r0 + 8) * HW + c) = v1;
            if (mt == 0) {
                float2 r2a, r2b;
                r2a.x = rndf(v0.x); r2a.y = rndf(v0.y);
                r2b.x = rndf(v1.x); r2b.y = rndf(v1.y);
                *(float2*)(fr + (size_t)r0 * HW + c)       = r2a;
                *(float2*)(fr + (size_t)(r0 + 8) * HW + c) = r2b;
            }
        }
    }
}

// ---------------------------------------------------------------------------
// Kernel 2: 3x3 conv 128 -> 384 pad=1, ReLU -> g_rpn_conv1 (rounded).
// Same 4-stage A-ring + fragment pipeline as conv1. H: 2 buffers at kc
// cadence (commit at tap==0 of kc -> drained many iters before first read).
// H slice: [8 zero pad][4 rows of 68], cols 64..67 zeroed.
// ---------------------------------------------------------------------------
#define H_ROW   68
#define H_PAD   8
#define H_SLICE 280                 // 8 pad + 4*68
#define H_BUFN  (16 * H_SLICE)      // 4480 floats per buffer
#define C3_AS   (128 * 20)          // 2560 floats per stage
#define C3_SMEM ((4 * C3_AS + 2 * H_BUFN) * 4)   // 76800 bytes

__global__ __launch_bounds__(128, 2)
void k_conv3(const float* __restrict__ b_c1)
{
    extern __shared__ float ds[];
    float* Asb = ds;                 // 4 stages of [128][20]
    float* Hb  = ds + 4 * C3_AS;

    const int n  = blockIdx.z;
    const int m0 = blockIdx.y * 128;
    const int n0 = blockIdx.x * 128;
    const int y0 = blockIdx.x * 2;
    const float* In = g_featr + (size_t)n * 128 * HW;

    const int tid  = threadIdx.x;
    const int warp = tid >> 5, lane = tid & 31;
    const int wm = (warp >> 1) * 64, wn = (warp & 1) * 64;
    const int g  = lane >> 2, t4 = lane & 3;

    // zero pads: per (buf,k): front pad [0..7] + halo cols 64..67 of 4 rows
    for (int i = tid; i < 768; i += 128) {
        int buf = i / 384, r2 = i % 384;
        int k = r2 / 24, e = r2 % 24;
        int off;
        if (e < 8) off = e;
        else { int rr = (e - 8) >> 2, cc = (e - 8) & 3;
               off = H_PAD + rr * H_ROW + 64 + cc; }
        Hb[buf * H_BUFN + k * H_SLICE + off] = 0.f;
    }

    auto loadA = [&](int t) {                     // t = iteration index
        int kc = t / 9, tap = t - kc * 9;
        float* As = Asb + (t & 3) * C3_AS;
        #pragma unroll
        for (int j = 0; j < 4; j++) {
            int e = tid + j * 128;                 // 0..511
            int row = e >> 2, u = e & 3;
            cp16(sptr(As + row * 20 + u * 4),
                 g_wt + ((size_t)tap * 384 + m0 + row) * 128 + kc * 16 + u * 4, true);
        }
    };
    auto loadH = [&](int kc, int buf) {
        #pragma unroll
        for (int j = 0; j < 8; j++) {
            int e = tid + j * 128;                 // 0..1023
            int k = e >> 6, rem = e & 63, r = rem >> 4, xu = rem & 15;
            int gy = y0 - 1 + r;
            cp16(sptr(&Hb[buf * H_BUFN + k * H_SLICE + H_PAD + r * H_ROW + xu * 4]),
                 In + (size_t)(kc * 16 + k) * HW + gy * 64 + xu * 4,
                 (unsigned)gy < 64u);
        }
    };

    int ib[8];
    #pragma unroll
    for (int nf = 0; nf < 8; nf++) {
        int px = wn + nf * 8 + g;
        ib[nf] = H_PAD + (1 + (px >> 6)) * H_ROW + (px & 63);
    }

    auto ldfrag = [&](const float* As, const float* Hc, int kk, int hoff,
                      unsigned (&a)[4][4], unsigned (&b)[8][2]) {
        #pragma unroll
        for (int mf = 0; mf < 4; mf++) {
            int r = wm + mf * 16;
            a[mf][0] = __float_as_uint(As[(r + g) * 20 + kk + t4]);
            a[mf][1] = __float_as_uint(As[(r + g + 8) * 20 + kk + t4]);
            a[mf][2] = __float_as_uint(As[(r + g) * 20 + kk + t4 + 4]);
            a[mf][3] = __float_as_uint(As[(r + g + 8) * 20 + kk + t4 + 4]);
        }
        #pragma unroll
        for (int nf = 0; nf < 8; nf++) {
            b[nf][0] = __float_as_uint(Hc[(kk + t4) * H_SLICE + ib[nf] + hoff]);
            b[nf][1] = __float_as_uint(Hc[(kk + t4 + 4) * H_SLICE + ib[nf] + hoff]);
        }
    };

    float acc[4][8][4] = {};
    unsigned aA[4][4], bA[8][2], aB[4][4], bB[8][2];

    // prologue groups: {A0,H0}, {A1}, {A2}
    loadA(0); loadH(0, 0); cpcommit();
    loadA(1); cpcommit();
    loadA(2); cpcommit();
    cpwait2();                                    // group0 (A0+H0) done
    __syncthreads();                              // ... visible (also pads)
    ldfrag(Asb, Hb, 0, -H_ROW - 1, aA, bA);       // ks0 of t=0 (tap0: dy=dx=-1)

    for (int it = 0; it < 72; it++) {
        const int kc = it / 9, tap = it - kc * 9;
        cpwait1();                                // stages <= it+1 complete
        __syncthreads();
        {
            if (it + 3 < 72) loadA(it + 3);
            if (tap == 0 && kc < 7) loadH(kc + 1, (kc + 1) & 1);
            cpcommit();
        }

        const int dy = tap / 3 - 1, dx = tap % 3 - 1;
        const int hoff = dy * H_ROW + dx;
        const float* As = Asb + (it & 3) * C3_AS;
        const float* Hc = Hb + (kc & 1) * H_BUFN;

        ldfrag(As, Hc, 8, hoff, aB, bB);           // ks1 of it
        #pragma unroll
        for (int mf = 0; mf < 4; mf++)
            #pragma unroll
            for (int nf = 0; nf < 8; nf++)
                mma8(acc[mf][nf], aA[mf], bA[nf]);
        if (it + 1 < 72) {
            int t1 = it + 1;
            int kc1 = t1 / 9, tap1 = t1 - kc1 * 9;
            int hoff1 = (tap1 / 3 - 1) * H_ROW + (tap1 % 3 - 1);
            ldfrag(Asb + (t1 & 3) * C3_AS, Hb + (kc1 & 1) * H_BUFN,
                   0, hoff1, aA, bA);              // ks0 of it+1
        }
        #pragma unroll
        for (int mf = 0; mf < 4; mf++)
            #pragma unroll
            for (int nf = 0; nf < 8; nf++)
                mma8(acc[mf][nf], aB[mf], bB[nf]);
    }

    float* ob = g_rpn_conv1 + (size_t)n * 384 * HW;
    #pragma unroll
    for (int mf = 0; mf < 4; mf++) {
        int r0 = m0 + wm + mf * 16 + g;
        float bv0 = b_c1[r0], bv1 = b_c1[r0 + 8];
        #pragma unroll
        for (int nf = 0; nf < 8; nf++) {
            int c = n0 + wn + nf * 8 + t4 * 2;
            float2 v0, v1;
            v0.x = rndf(fmaxf(acc[mf][nf][0] + bv0, 0.f));
            v0.y = rndf(fmaxf(acc[mf][nf][1] + bv0, 0.f));
            v1.x = rndf(fmaxf(acc[mf][nf][2] + bv1, 0.f));
            v1.y = rndf(fmaxf(acc[mf][nf][3] + bv1, 0.f));
            *(float2*)(ob + (size_t)r0 * HW + c)       = v0;
            *(float2*)(ob + (size_t)(r0 + 8) * HW + c) = v1;
        }
    }
}

// ---------------------------------------------------------------------------
// Kernel 3: head. 128 threads, 4 warps of 32x64 (2M x 2N). K-tile 16,
// 4-stage ring + fragment pipeline (same scheme). Bias + paired softmax
// (c, c+9) for cls, bias for box, two zero scalars. Cs overlays the ring
// (extra sync before the overlay write).
// ---------------------------------------------------------------------------
#define HD_A_ST (64 * 20)               // 1280
#define HD_B_ST (16 * 136)              // 2176
#define HD_STAGE (HD_A_ST + HD_B_ST)    // 3456 floats
#define HD_SMEM (4 * HD_STAGE * 4)      // 55296 bytes

__global__ __launch_bounds__(128)
void k_head(const float* __restrict__ b_cls, const float* __restrict__ b_box,
            float* __restrict__ out)
{
    extern __shared__ float ds[];
    const int n  = blockIdx.z;
    const int n0 = blockIdx.x * 128;
    const float* Bp = g_rpn_conv1 + (size_t)n * 384 * HW + n0;

    const int tid  = threadIdx.x;
    const int warp = tid >> 5, lane = tid & 31;
    const int wm = (warp >> 1) * 32, wn = (warp & 1) * 64;
    const int g  = lane >> 2, t4 = lane & 3;

    auto loadT = [&](int t) {
        float* As = ds + (t & 3) * HD_STAGE;
        float* Bs = As + HD_A_ST;
        const int k0 = t * 16;
        #pragma unroll
        for (int j = 0; j < 2; j++) {
            int e = tid + j * 128;                // 0..255
            cp16(sptr(As + (e >> 2) * 20 + (e & 3) * 4),
                 g_wh + (size_t)(e >> 2) * 384 + k0 + (e & 3) * 4, true);
        }
        #pragma unroll
        for (int j = 0; j < 4; j++) {
            int e = tid + j * 128;                // 0..511
            cp16(sptr(Bs + (e >> 5) * 136 + (e & 31) * 4),
                 Bp + (size_t)(k0 + (e >> 5)) * HW + (e & 31) * 4, true);
        }
        cpcommit();
    };

    auto ldfrag = [&](const float* As, const float* Bs, int kk,
                      unsigned (&a)[2][4], unsigned (&b)[8][2]) {
        #pragma unroll
        for (int mf = 0; mf < 2; mf++) {
            int r = wm + mf * 16;
            a[mf][0] = __float_as_uint(As[(r + g) * 20 + kk + t4]);
            a[mf][1] = __float_as_uint(As[(r + g + 8) * 20 + kk + t4]);
            a[mf][2] = __float_as_uint(As[(r + g) * 20 + kk + t4 + 4]);
            a[mf][3] = __float_as_uint(As[(r + g + 8) * 20 + kk + t4 + 4]);
        }
        #pragma unroll
        for (int nf = 0; nf < 8; nf++) {
            int c = wn + nf * 8 + g;
            b[nf][0] = __float_as_uint(Bs[(kk + t4) * 136 + c]);
            b[nf][1] = __float_as_uint(Bs[(kk + t4 + 4) * 136 + c]);
        }
    };

    float acc[2][8][4] = {};
    unsigned aA[2][4], bA[8][2], aB[2][4], bB[8][2];

    loadT(0); loadT(1); loadT(2);
    cpwait2();
    __syncthreads();
    ldfrag(ds, ds + HD_A_ST, 0, aA, bA);

    for (int t = 0; t < 24; t++) {
        cpwait1();
        __syncthreads();
        if (t + 3 < 24) loadT(t + 3); else cpcommit();

        const float* As = ds + (t & 3) * HD_STAGE;
        ldfrag(As, As + HD_A_ST, 8, aB, bB);
        #pragma unroll
        for (int mf = 0; mf < 2; mf++)
            #pragma unroll
            for (int nf = 0; nf < 8; nf++)
                mma8(acc[mf][nf], aA[mf], bA[nf]);
        if (t + 1 < 24) {
            const float* As2 = ds + ((t + 1) & 3) * HD_STAGE;
            ldfrag(As2, As2 + HD_A_ST, 0, aA, bA);
        }
        #pragma unroll
        for (int mf = 0; mf < 2; mf++)
            #pragma unroll
            for (int nf = 0; nf < 8; nf++)
                mma8(acc[mf][nf], aB[mf], bB[nf]);
    }

    __syncthreads();                       // all warps done reading ring
    float (*Cs)[132] = (float(*)[132])ds;  // overlay
    #pragma unroll
    for (int mf = 0; mf < 2; mf++) {
        int r0 = wm + mf * 16 + g;
        #pragma unroll
        for (int nf = 0; nf < 8; nf++) {
            int c = wn + nf * 8 + t4 * 2;
            Cs[r0][c]         = acc[mf][nf][0];
            Cs[r0][c + 1]     = acc[mf][nf][1];
            Cs[r0 + 8][c]     = acc[mf][nf][2];
            Cs[r0 + 8][c + 1] = acc[mf][nf][3];
        }
    }
    __syncthreads();

    const size_t F1 = (size_t)CB * CIN * HW;
    const size_t F2 = F1 + (size_t)CB * 18 * HW;
    const size_t F3 = F2 + (size_t)CB * 36 * HW;

    for (int it = tid; it < 9 * 128; it += 128) {
        int c = it >> 7, j = it & 127;
        float s0 = Cs[c][j]     + b_cls[c];
        float s1 = Cs[c + 9][j] + b_cls[c + 9];
        float m  = fmaxf(s0, s1);
        float e0 = expf(s0 - m), e1 = expf(s1 - m);
        float inv = 1.f / (e0 + e1);
        out[F1 + (size_t)n * 18 * HW + (size_t)c * HW + n0 + j]       = e0 * inv;
        out[F1 + (size_t)n * 18 * HW + (size_t)(c + 9) * HW + n0 + j] = e1 * inv;
    }
    for (int it = tid; it < 36 * 128; it += 128) {
        int c = it >> 7, j = it & 127;
        out[F2 + (size_t)n * 36 * HW + (size_t)c * HW + n0 + j] = Cs[18 + c][j] + b_box[c];
    }
    if (n == 0 && blockIdx.x == 0 && tid == 0) {
        out[F3]     = 0.f;
        out[F3 + 1] = 0.f;
    }
}

// ---------------------------------------------------------------------------
extern "C" void kernel_launch(void* const* d_in, const int* in_sizes, int n_in,
                              void* d_out, int out_size)
{
    const float* base  = (const float*)d_in[0];
    const float* w_f   = (const float*)d_in[3];
    const float* b_f   = (const float*)d_in[4];
    const float* w_2   = (const float*)d_in[5];
    const float* b_2   = (const float*)d_in[6];
    const float* w_c1  = (const float*)d_in[7];
    const float* b_c1  = (const float*)d_in[8];
    const float* w_cls = (const float*)d_in[9];
    const float* b_cls = (const float*)d_in[10];
    const float* w_box = (const float*)d_in[11];
    const float* b_box = (const float*)d_in[12];
    float* out = (float*)d_out;

    static bool attr_set = false;
    if (!attr_set) {
        cudaFuncSetAttribute(k_conv1, cudaFuncAttributeMaxDynamicSharedMemorySize, C1_SMEM);
        cudaFuncSetAttribute(k_conv3, cudaFuncAttributeMaxDynamicSharedMemorySize, C3_SMEM);
        cudaFuncSetAttribute(k_head,  cudaFuncAttributeMaxDynamicSharedMemorySize, HD_SMEM);
        attr_set = true;
    }

    k_prep <<<(PREP_TOT + 255) / 256, 256>>>(w_f, w_2, w_c1, w_cls, w_box);
    k_conv1<<<dim3(32, 4, CB), 128, C1_SMEM>>>(base, b_f, b_2, out);
    k_conv3<<<dim3(32, 3, CB), 128, C3_SMEM>>>(b_c1);
    k_head <<<dim3(32, 1, CB), 128, HD_SMEM>>>(b_cls, b_box, out);
}